// round 1
// baseline (speedup 1.0000x reference)
#include <cuda_runtime.h>
#include <math.h>

// Problem constants
#define BATCHN 2
#define SEQ    2048
#define EMB    2048
#define NH     16
#define HD     128
#define MTOT   (BATCHN * SEQ)   // 4096

// Scratch buffers (static device globals: allocation-free)
__device__ float g_q[BATCHN * NH * SEQ * HD];   // [B,H,S,D]
__device__ float g_k[BATCHN * NH * SEQ * HD];   // [B,H,S,D]
__device__ float g_v[BATCHN * NH * SEQ * HD];   // [B,H,S,D]
__device__ float g_att[BATCHN * SEQ * NH * HD]; // [B,S,H*D]

// ---------------------------------------------------------------------------
// SGEMM: C[M=4096, N=2048] = A[4096,2048] @ B[2048,2048], fp32, row-major.
// 128x128 block tile, 8-deep k panels, 8x8 per-thread microtile, 256 threads.
// MODE 0: plain row-major store.
// MODE 1: QKV permute store -> out[((b*NH+h)*SEQ+s)*HD + d]
// ---------------------------------------------------------------------------
template <int MODE>
__global__ __launch_bounds__(256, 2)
void sgemm128(const float* __restrict__ A, const float* __restrict__ B,
              float* __restrict__ C)
{
    const int K = EMB, N = EMB;
    __shared__ float As[8 * 128];   // [k][row]
    __shared__ float Bs[8 * 128];   // [k][col]

    const int tid = threadIdx.x;
    const int m0 = blockIdx.y * 128;
    const int n0 = blockIdx.x * 128;
    const int ty = tid >> 4;        // 0..15
    const int tx = tid & 15;        // 0..15

    const int arow = tid >> 1;          // 0..127
    const int ac4  = (tid & 1) * 4;     // 0 or 4
    const int brow = tid >> 5;          // 0..7
    const int bc4  = (tid & 31) * 4;    // 0..124

    const float* Ap = A + (size_t)(m0 + arow) * K + ac4;
    const float* Bp = B + (size_t)brow * N + n0 + bc4;

    float acc[8][8];
#pragma unroll
    for (int i = 0; i < 8; i++)
#pragma unroll
        for (int j = 0; j < 8; j++) acc[i][j] = 0.f;

    for (int kt = 0; kt < K; kt += 8) {
        float4 av = *(const float4*)(Ap + kt);
        float4 bv = *(const float4*)(Bp + (size_t)kt * N);
        __syncthreads();   // previous compute done before smem overwrite
        As[(ac4 + 0) * 128 + arow] = av.x;
        As[(ac4 + 1) * 128 + arow] = av.y;
        As[(ac4 + 2) * 128 + arow] = av.z;
        As[(ac4 + 3) * 128 + arow] = av.w;
        *(float4*)&Bs[brow * 128 + bc4] = bv;
        __syncthreads();

#pragma unroll
        for (int kk = 0; kk < 8; kk++) {
            float a[8], b[8];
            *(float4*)(a)     = *(const float4*)&As[kk * 128 + ty * 8];
            *(float4*)(a + 4) = *(const float4*)&As[kk * 128 + ty * 8 + 4];
            *(float4*)(b)     = *(const float4*)&Bs[kk * 128 + tx * 8];
            *(float4*)(b + 4) = *(const float4*)&Bs[kk * 128 + tx * 8 + 4];
#pragma unroll
            for (int i = 0; i < 8; i++)
#pragma unroll
                for (int j = 0; j < 8; j++)
                    acc[i][j] = fmaf(a[i], b[j], acc[i][j]);
        }
    }

    // Epilogue
#pragma unroll
    for (int i = 0; i < 8; i++) {
        int m = m0 + ty * 8 + i;
        float4 v0 = make_float4(acc[i][0], acc[i][1], acc[i][2], acc[i][3]);
        float4 v1 = make_float4(acc[i][4], acc[i][5], acc[i][6], acc[i][7]);
        if (MODE == 0) {
            float* p = C + (size_t)m * N + n0 + tx * 8;
            *(float4*)p       = v0;
            *(float4*)(p + 4) = v1;
        } else {
            int b = m >> 11;          // SEQ = 2048
            int s = m & 2047;
            int h = n0 >> 7;          // block tile spans exactly one head
            int d = tx * 8;
            float* p = C + ((size_t)(b * NH + h) * SEQ + s) * HD + d;
            *(float4*)p       = v0;
            *(float4*)(p + 4) = v1;
        }
    }
}

// ---------------------------------------------------------------------------
// RoPE in-place on g_q and g_k.  d in [0,64): pairs (d, d+64).
// ---------------------------------------------------------------------------
__global__ void rope_kernel(const float* __restrict__ cosp,
                            const float* __restrict__ sinp)
{
    int gid = blockIdx.x * blockDim.x + threadIdx.x;  // < B*NH*SEQ*64
    int d  = gid & 63;
    int s  = (gid >> 6) & (SEQ - 1);
    int bh = gid >> 17;              // SEQ*64 = 2^17
    int b  = bh >> 4;                // NH = 16

    int co = (b * SEQ + s) * HD;
    float c1 = cosp[co + d],      s1 = sinp[co + d];
    float c2 = cosp[co + d + 64], s2 = sinp[co + d + 64];

    size_t qo = ((size_t)bh * SEQ + s) * HD + d;
    float x1 = g_q[qo], x2 = g_q[qo + 64];
    g_q[qo]      = x1 * c1 - x2 * s1;
    g_q[qo + 64] = x2 * c2 + x1 * s2;
    x1 = g_k[qo]; x2 = g_k[qo + 64];
    g_k[qo]      = x1 * c1 - x2 * s1;
    g_k[qo + 64] = x2 * c2 + x1 * s2;
}

// ---------------------------------------------------------------------------
// Causal flash attention, fp32. BM=BN=64, D=128, 256 threads.
// smem: Qs[128][64] d-major, Ks[128][64] d-major, Vs[64][128], Ps[64][64] (c,r)
// Thread (ty,tx): score tile rows ty*4.., cols tx*4.. ; O tile rows ty*4..,
// dv = tx*8.. ; per-row softmax state replicated across tx within 16-lane group.
// ---------------------------------------------------------------------------
__global__ __launch_bounds__(256)
void attn_kernel()
{
    extern __shared__ float sm[];
    float* Qs = sm;              // 128*64
    float* Ks = sm + 8192;       // 128*64
    float* Vs = sm + 16384;      // 64*128
    float* Ps = sm + 24576;      // 64*64

    const int tid = threadIdx.x;
    const int qt  = blockIdx.x;        // 0..31
    const int bh  = blockIdx.y;        // 0..31
    const int qbase = qt * 64;

    const float* Qg = g_q + ((size_t)bh * SEQ + qbase) * HD;
    const float qscale = 0.08838834764831845f;  // 1/sqrt(128)

    // Load Q tile (pre-scaled), transposed to d-major
#pragma unroll
    for (int i = 0; i < 8; i++) {
        int idx = i * 256 + tid;       // float4 index, 0..2047
        int row = idx >> 5;
        int c4  = (idx & 31) << 2;
        float4 v = *(const float4*)(Qg + row * HD + c4);
        Qs[(c4 + 0) * 64 + row] = v.x * qscale;
        Qs[(c4 + 1) * 64 + row] = v.y * qscale;
        Qs[(c4 + 2) * 64 + row] = v.z * qscale;
        Qs[(c4 + 3) * 64 + row] = v.w * qscale;
    }

    const int ty = tid >> 4, tx = tid & 15;
    const int r0 = ty * 4, c0 = tx * 4;

    float o[4][8];
#pragma unroll
    for (int i = 0; i < 4; i++)
#pragma unroll
        for (int j = 0; j < 8; j++) o[i][j] = 0.f;
    float mstate[4] = {-1e30f, -1e30f, -1e30f, -1e30f};
    float lstate[4] = {0.f, 0.f, 0.f, 0.f};

    for (int kt = 0; kt <= qt; kt++) {
        const float* Kg = g_k + ((size_t)bh * SEQ + kt * 64) * HD;
        const float* Vg = g_v + ((size_t)bh * SEQ + kt * 64) * HD;

        __syncthreads();  // prev PV done before overwriting Ks/Vs/Ps
#pragma unroll
        for (int i = 0; i < 8; i++) {
            int idx = i * 256 + tid;
            int row = idx >> 5;
            int c4  = (idx & 31) << 2;
            float4 kv = *(const float4*)(Kg + row * HD + c4);
            Ks[(c4 + 0) * 64 + row] = kv.x;
            Ks[(c4 + 1) * 64 + row] = kv.y;
            Ks[(c4 + 2) * 64 + row] = kv.z;
            Ks[(c4 + 3) * 64 + row] = kv.w;
            float4 vv = *(const float4*)(Vg + row * HD + c4);
            *(float4*)&Vs[row * 128 + c4] = vv;
        }
        __syncthreads();

        // S = Qs^T * Ks  (both d-major)
        float s[4][4];
#pragma unroll
        for (int i = 0; i < 4; i++)
#pragma unroll
            for (int j = 0; j < 4; j++) s[i][j] = 0.f;
#pragma unroll 4
        for (int d = 0; d < 128; d++) {
            float4 a = *(const float4*)&Qs[d * 64 + r0];
            float4 b = *(const float4*)&Ks[d * 64 + c0];
            float av[4] = {a.x, a.y, a.z, a.w};
            float bv[4] = {b.x, b.y, b.z, b.w};
#pragma unroll
            for (int i = 0; i < 4; i++)
#pragma unroll
                for (int j = 0; j < 4; j++)
                    s[i][j] = fmaf(av[i], bv[j], s[i][j]);
        }

        if (kt == qt) {
            // diagonal tile: mask cols > rows (same 64-base)
#pragma unroll
            for (int i = 0; i < 4; i++)
#pragma unroll
                for (int j = 0; j < 4; j++)
                    if (c0 + j > r0 + i) s[i][j] = -1e30f;
        }

        // online softmax per row (reduce across 16 tx lanes)
#pragma unroll
        for (int i = 0; i < 4; i++) {
            float mx = s[i][0];
            mx = fmaxf(mx, s[i][1]);
            mx = fmaxf(mx, s[i][2]);
            mx = fmaxf(mx, s[i][3]);
#pragma unroll
            for (int off = 8; off >= 1; off >>= 1)
                mx = fmaxf(mx, __shfl_xor_sync(0xffffffffu, mx, off, 16));
            float mnew = fmaxf(mstate[i], mx);
            float corr = __expf(mstate[i] - mnew);
            float p0 = __expf(s[i][0] - mnew);
            float p1 = __expf(s[i][1] - mnew);
            float p2 = __expf(s[i][2] - mnew);
            float p3 = __expf(s[i][3] - mnew);
            float rs = p0 + p1 + p2 + p3;
#pragma unroll
            for (int off = 8; off >= 1; off >>= 1)
                rs += __shfl_xor_sync(0xffffffffu, rs, off, 16);
            lstate[i] = lstate[i] * corr + rs;
            mstate[i] = mnew;
#pragma unroll
            for (int j = 0; j < 8; j++) o[i][j] *= corr;
            Ps[(c0 + 0) * 64 + r0 + i] = p0;
            Ps[(c0 + 1) * 64 + r0 + i] = p1;
            Ps[(c0 + 2) * 64 + r0 + i] = p2;
            Ps[(c0 + 3) * 64 + r0 + i] = p3;
        }
        __syncthreads();

        // O += P * V
#pragma unroll 4
        for (int c = 0; c < 64; c++) {
            float4 a  = *(const float4*)&Ps[c * 64 + r0];
            float4 b0 = *(const float4*)&Vs[c * 128 + tx * 8];
            float4 b1 = *(const float4*)&Vs[c * 128 + tx * 8 + 4];
            float av[4] = {a.x, a.y, a.z, a.w};
            float bv[8] = {b0.x, b0.y, b0.z, b0.w, b1.x, b1.y, b1.z, b1.w};
#pragma unroll
            for (int i = 0; i < 4; i++)
#pragma unroll
                for (int j = 0; j < 8; j++)
                    o[i][j] = fmaf(av[i], bv[j], o[i][j]);
        }
    }

    // epilogue: normalize and write [B,S,H,D]
    int b = bh >> 4, h = bh & 15;
#pragma unroll
    for (int i = 0; i < 4; i++) {
        float inv = 1.f / lstate[i];
        int srow = qbase + r0 + i;
        float* p = g_att + ((size_t)(b * SEQ + srow) * NH + h) * HD + tx * 8;
        float4 v0 = make_float4(o[i][0] * inv, o[i][1] * inv,
                                o[i][2] * inv, o[i][3] * inv);
        float4 v1 = make_float4(o[i][4] * inv, o[i][5] * inv,
                                o[i][6] * inv, o[i][7] * inv);
        *(float4*)p       = v0;
        *(float4*)(p + 4) = v1;
    }
}

// ---------------------------------------------------------------------------
// Launcher
// ---------------------------------------------------------------------------
extern "C" void kernel_launch(void* const* d_in, const int* in_sizes, int n_in,
                              void* d_out, int out_size)
{
    (void)in_sizes; (void)n_in; (void)out_size;
    const float* X    = (const float*)d_in[0];
    const float* cosp = (const float*)d_in[1];
    const float* sinp = (const float*)d_in[2];
    const float* Wq   = (const float*)d_in[3];
    const float* Wk   = (const float*)d_in[4];
    const float* Wv   = (const float*)d_in[5];
    const float* Wo   = (const float*)d_in[6];
    float* out = (float*)d_out;

    float *q, *k, *v, *att;
    cudaGetSymbolAddress((void**)&q,   g_q);
    cudaGetSymbolAddress((void**)&k,   g_k);
    cudaGetSymbolAddress((void**)&v,   g_v);
    cudaGetSymbolAddress((void**)&att, g_att);

    dim3 gg(EMB / 128, MTOT / 128);   // (16, 32)
    sgemm128<1><<<gg, 256>>>(X, Wq, q);
    sgemm128<1><<<gg, 256>>>(X, Wk, k);
    sgemm128<1><<<gg, 256>>>(X, Wv, v);

    rope_kernel<<<(BATCHN * NH * SEQ * 64) / 256, 256>>>(cosp, sinp);

    cudaFuncSetAttribute(attn_kernel,
                         cudaFuncAttributeMaxDynamicSharedMemorySize, 114688);
    attn_kernel<<<dim3(32, 32), 256, 114688>>>();

    sgemm128<0><<<gg, 256>>>(att, Wo, out);
}

// round 4
// speedup vs baseline: 1.3362x; 1.3362x over previous
#include <cuda_runtime.h>
#include <cuda_bf16.h>
#include <math.h>
#include <cstdint>

// Problem constants
#define BATCHN 2
#define SEQ    2048
#define EMB    2048
#define NH     16
#define HD     128
#define MTOT   (BATCHN * SEQ)   // 4096
#define BK     32
#define KITERS (EMB / BK)       // 64

// ---------------------------------------------------------------------------
// Scratch (static device globals: allocation-free)
// ---------------------------------------------------------------------------
__device__ float g_q[BATCHN * NH * SEQ * HD];    // [B,H,S,D]
__device__ float g_k[BATCHN * NH * SEQ * HD];    // [B,H,S,D]
__device__ float g_v[BATCHN * NH * SEQ * HD];    // [B,H,S,D]
__device__ float g_att[BATCHN * SEQ * NH * HD];  // [B,S,H*D]
__device__ __nv_bfloat16 g_xh[MTOT * EMB];       // X split hi
__device__ __nv_bfloat16 g_xl[MTOT * EMB];       // X split lo
__device__ __nv_bfloat16 g_ath[MTOT * EMB];      // att split hi
__device__ __nv_bfloat16 g_atl[MTOT * EMB];      // att split lo
__device__ __nv_bfloat16 g_wh[4 * EMB * EMB];    // W^T split hi, [n][k]
__device__ __nv_bfloat16 g_wl[4 * EMB * EMB];    // W^T split lo, [n][k]

// ---------------------------------------------------------------------------
// Helpers
// ---------------------------------------------------------------------------
__device__ __forceinline__ uint32_t smem_u32(const void* p) {
    uint32_t a;
    asm("{ .reg .u64 t; cvta.to.shared.u64 t, %1; cvt.u32.u64 %0, t; }"
        : "=r"(a) : "l"(p));
    return a;
}

__device__ __forceinline__ void ldm_x4(uint32_t& r0, uint32_t& r1,
                                       uint32_t& r2, uint32_t& r3, uint32_t a) {
    asm volatile("ldmatrix.sync.aligned.m8n8.x4.shared.b16 {%0,%1,%2,%3}, [%4];"
                 : "=r"(r0), "=r"(r1), "=r"(r2), "=r"(r3) : "r"(a));
}

__device__ __forceinline__ void mma_bf16(float* c, uint32_t a0, uint32_t a1,
                                         uint32_t a2, uint32_t a3,
                                         uint32_t b0, uint32_t b1) {
    asm volatile("mma.sync.aligned.m16n8k16.row.col.f32.bf16.bf16.f32 "
                 "{%0,%1,%2,%3}, {%4,%5,%6,%7}, {%8,%9}, {%0,%1,%2,%3};"
                 : "+f"(c[0]), "+f"(c[1]), "+f"(c[2]), "+f"(c[3])
                 : "r"(a0), "r"(a1), "r"(a2), "r"(a3), "r"(b0), "r"(b1));
}

// ---------------------------------------------------------------------------
// Split fp32 -> bf16 hi + bf16 lo (elementwise), 4 floats per thread
// ---------------------------------------------------------------------------
__global__ void split_kernel(const float* __restrict__ src,
                             __nv_bfloat16* __restrict__ dh,
                             __nv_bfloat16* __restrict__ dl)
{
    int i = blockIdx.x * blockDim.x + threadIdx.x;   // float4 index
    float4 v = ((const float4*)src)[i];
    __nv_bfloat16 h0 = __float2bfloat16(v.x);
    __nv_bfloat16 h1 = __float2bfloat16(v.y);
    __nv_bfloat16 h2 = __float2bfloat16(v.z);
    __nv_bfloat16 h3 = __float2bfloat16(v.w);
    __nv_bfloat16 l0 = __float2bfloat16(v.x - __bfloat162float(h0));
    __nv_bfloat16 l1 = __float2bfloat16(v.y - __bfloat162float(h1));
    __nv_bfloat16 l2 = __float2bfloat16(v.z - __bfloat162float(h2));
    __nv_bfloat16 l3 = __float2bfloat16(v.w - __bfloat162float(h3));
    __nv_bfloat162* ph = (__nv_bfloat162*)dh;
    __nv_bfloat162* pl = (__nv_bfloat162*)dl;
    ph[2 * i]     = __halves2bfloat162(h0, h1);
    ph[2 * i + 1] = __halves2bfloat162(h2, h3);
    pl[2 * i]     = __halves2bfloat162(l0, l1);
    pl[2 * i + 1] = __halves2bfloat162(l2, l3);
}

// ---------------------------------------------------------------------------
// Transpose + split weights: g_wh/g_wl[z][n*EMB + k] = split(W_z[k*EMB + n])
// ---------------------------------------------------------------------------
__global__ void wsplit_kernel(const float* __restrict__ Wq,
                              const float* __restrict__ Wk,
                              const float* __restrict__ Wv,
                              const float* __restrict__ Wo)
{
    __shared__ float t[32][33];
    const int z = blockIdx.z;
    const float* W = (z == 0) ? Wq : (z == 1) ? Wk : (z == 2) ? Wv : Wo;
    __nv_bfloat16* Oh = g_wh + (size_t)z * EMB * EMB;
    __nv_bfloat16* Ol = g_wl + (size_t)z * EMB * EMB;

    int x  = blockIdx.x * 32 + threadIdx.x;   // col n
    int y0 = blockIdx.y * 32;                 // row k
#pragma unroll
    for (int j = 0; j < 32; j += 8)
        t[threadIdx.y + j][threadIdx.x] = W[(size_t)(y0 + threadIdx.y + j) * EMB + x];
    __syncthreads();
    int ox = y0 + threadIdx.x;                // k index (contiguous out)
#pragma unroll
    for (int j = 0; j < 32; j += 8) {
        int oy = blockIdx.x * 32 + threadIdx.y + j;   // n index
        float val = t[threadIdx.x][threadIdx.y + j];
        __nv_bfloat16 h = __float2bfloat16(val);
        __nv_bfloat16 l = __float2bfloat16(val - __bfloat162float(h));
        Oh[(size_t)oy * EMB + ox] = h;
        Ol[(size_t)oy * EMB + ox] = l;
    }
}

// ---------------------------------------------------------------------------
// bf16 3-term GEMM via mma.sync: C[4096,2048] = A @ Bt^T
//   A split: Ah/Al [m][k] bf16.  Bt split: Bh/Bl [n][k] bf16 (pre-transposed W).
// 128x128 block tile, BK=32, 3-stage cp.async pipeline, SW128 swizzle,
// ldmatrix fragment loads, mma m16n8k16 (hh + hl + lh).
// MODE 0: row-major C.  MODE 1: QKV permute -> [B,H,S,D].
// smem stage (32KB): A tile 128 rows x 128B (64B hi | 64B lo), B tile same.
// ---------------------------------------------------------------------------
template <int MODE>
__global__ __launch_bounds__(256)
void gemm_bf16(const __nv_bfloat16* __restrict__ Ah,
               const __nv_bfloat16* __restrict__ Al,
               const __nv_bfloat16* __restrict__ Bh,
               const __nv_bfloat16* __restrict__ Bl,
               float* __restrict__ C)
{
    extern __shared__ char smem[];
    const uint32_t sa = smem_u32(smem);
    const int tid  = threadIdx.x;
    const int lane = tid & 31;
    const int wid  = tid >> 5;
    const int m0 = blockIdx.y * 128;
    const int n0 = blockIdx.x * 128;

    // cp.async source roles: thread -> (row r, half: 0=hi 1=lo), 4x16B chunks
    const int r    = tid >> 1;
    const int half = tid & 1;
    const __nv_bfloat16* agm = (half ? Al : Ah) + (size_t)(m0 + r) * EMB;
    const __nv_bfloat16* bgm = (half ? Bl : Bh) + (size_t)(n0 + r) * EMB;
    const uint32_t swr   = (uint32_t)((r & 7) << 4);
    const uint32_t ainner = (uint32_t)(half * 64);

    auto issue = [&](int it, int stage) {
        const int k0 = it * BK;
        const uint32_t abase = sa + stage * 32768 + r * 128;
        const uint32_t bbase = abase + 16384;
#pragma unroll
        for (int c = 0; c < 4; c++) {
            uint32_t sw = (ainner + c * 16) ^ swr;
            asm volatile("cp.async.cg.shared.global [%0], [%1], 16;"
                         :: "r"(abase + sw), "l"(agm + k0 + c * 8) : "memory");
            asm volatile("cp.async.cg.shared.global [%0], [%1], 16;"
                         :: "r"(bbase + sw), "l"(bgm + k0 + c * 8) : "memory");
        }
    };

    // Warp tile: wm in {0,64}, wn in {0,32,64,96}
    const int wm = (wid & 1) * 64;
    const int wn = (wid >> 1) * 32;
    // ldmatrix per-thread row/koff pieces
    const int arl = (lane & 7) + ((lane >> 3) & 1) * 8;   // A row-local
    const int koa = (lane >> 4) * 16;                     // A k byte offset
    const int brl = ((lane >> 4) & 1) * 8 + (lane & 7);   // B n-row-local
    const int kob = ((lane >> 3) & 1) * 16;               // B k byte offset

    float acc[4][4][4];
#pragma unroll
    for (int mt = 0; mt < 4; mt++)
#pragma unroll
        for (int nt = 0; nt < 4; nt++)
#pragma unroll
            for (int e = 0; e < 4; e++) acc[mt][nt][e] = 0.f;

    // Prologue: stages 0,1 in flight
    issue(0, 0);
    asm volatile("cp.async.commit_group;" ::: "memory");
    issue(1, 1);
    asm volatile("cp.async.commit_group;" ::: "memory");

#pragma unroll 1
    for (int it = 0; it < KITERS; it++) {
        if (it + 2 < KITERS) issue(it + 2, (it + 2) % 3);
        asm volatile("cp.async.commit_group;" ::: "memory");
        asm volatile("cp.async.wait_group 2;" ::: "memory");
        __syncthreads();

        const uint32_t ab = sa + (it % 3) * 32768;
        const uint32_t bb = ab + 16384;
#pragma unroll
        for (int s = 0; s < 2; s++) {
            uint32_t ah[4][4], al4[4][4], bhf[4][2], blf[4][2];
#pragma unroll
            for (int mt = 0; mt < 4; mt++) {
                const int row = wm + mt * 16 + arl;
                const uint32_t sw = (uint32_t)((row & 7) << 4);
                const uint32_t base = ab + row * 128;
                const uint32_t ih = (uint32_t)(s * 32 + koa);
                ldm_x4(ah[mt][0], ah[mt][1], ah[mt][2], ah[mt][3],
                       base + (ih ^ sw));
                ldm_x4(al4[mt][0], al4[mt][1], al4[mt][2], al4[mt][3],
                       base + ((ih + 64) ^ sw));
            }
#pragma unroll
            for (int np = 0; np < 2; np++) {
                const int row = wn + np * 16 + brl;
                const uint32_t sw = (uint32_t)((row & 7) << 4);
                const uint32_t base = bb + row * 128;
                const uint32_t ih = (uint32_t)(s * 32 + kob);
                uint32_t h0, h1, h2, h3, l0, l1, l2, l3;
                ldm_x4(h0, h1, h2, h3, base + (ih ^ sw));
                ldm_x4(l0, l1, l2, l3, base + ((ih + 64) ^ sw));
                bhf[np * 2][0] = h0; bhf[np * 2][1] = h1;
                bhf[np * 2 + 1][0] = h2; bhf[np * 2 + 1][1] = h3;
                blf[np * 2][0] = l0; blf[np * 2][1] = l1;
                blf[np * 2 + 1][0] = l2; blf[np * 2 + 1][1] = l3;
            }
#pragma unroll
            for (int mt = 0; mt < 4; mt++)
#pragma unroll
                for (int nt = 0; nt < 4; nt++) {
                    float* c = acc[mt][nt];
                    mma_bf16(c, ah[mt][0], ah[mt][1], ah[mt][2], ah[mt][3],
                             bhf[nt][0], bhf[nt][1]);
                    mma_bf16(c, ah[mt][0], ah[mt][1], ah[mt][2], ah[mt][3],
                             blf[nt][0], blf[nt][1]);
                    mma_bf16(c, al4[mt][0], al4[mt][1], al4[mt][2], al4[mt][3],
                             bhf[nt][0], bhf[nt][1]);
                }
        }
        __syncthreads();
    }

    // Epilogue
    const int g = lane >> 2, tig = lane & 3;
#pragma unroll
    for (int mt = 0; mt < 4; mt++) {
        const int m = m0 + wm + mt * 16 + g;
#pragma unroll
        for (int nt = 0; nt < 4; nt++) {
            const int col = wn + nt * 8 + 2 * tig;
            float2 v0 = make_float2(acc[mt][nt][0], acc[mt][nt][1]);
            float2 v1 = make_float2(acc[mt][nt][2], acc[mt][nt][3]);
            if (MODE == 0) {
                float* p = C + (size_t)m * EMB + n0 + col;
                *(float2*)p = v0;
                *(float2*)(p + (size_t)8 * EMB) = v1;
            } else {
                const int b = m >> 11, si = m & 2047, h = n0 >> 7;
                float* p = C + ((size_t)(b * NH + h) * SEQ + si) * HD + col;
                *(float2*)p = v0;
                *(float2*)(p + 8 * HD) = v1;
            }
        }
    }
}

// ---------------------------------------------------------------------------
// RoPE in-place on g_q and g_k.  d in [0,64): pairs (d, d+64).
// ---------------------------------------------------------------------------
__global__ void rope_kernel(const float* __restrict__ cosp,
                            const float* __restrict__ sinp)
{
    int gid = blockIdx.x * blockDim.x + threadIdx.x;
    int d  = gid & 63;
    int s  = (gid >> 6) & (SEQ - 1);
    int bh = gid >> 17;
    int b  = bh >> 4;

    int co = (b * SEQ + s) * HD;
    float c1 = cosp[co + d],      s1 = sinp[co + d];
    float c2 = cosp[co + d + 64], s2 = sinp[co + d + 64];

    size_t qo = ((size_t)bh * SEQ + s) * HD + d;
    float x1 = g_q[qo], x2 = g_q[qo + 64];
    g_q[qo]      = x1 * c1 - x2 * s1;
    g_q[qo + 64] = x2 * c2 + x1 * s2;
    x1 = g_k[qo]; x2 = g_k[qo + 64];
    g_k[qo]      = x1 * c1 - x2 * s1;
    g_k[qo + 64] = x2 * c2 + x1 * s2;
}

// ---------------------------------------------------------------------------
// Causal flash attention, fp32 (validated in round 1, unchanged).
// ---------------------------------------------------------------------------
__global__ __launch_bounds__(256)
void attn_kernel()
{
    extern __shared__ float sm[];
    float* Qs = sm;              // 128*64
    float* Ks = sm + 8192;       // 128*64
    float* Vs = sm + 16384;      // 64*128
    float* Ps = sm + 24576;      // 64*64

    const int tid = threadIdx.x;
    const int qt  = blockIdx.x;
    const int bh  = blockIdx.y;
    const int qbase = qt * 64;

    const float* Qg = g_q + ((size_t)bh * SEQ + qbase) * HD;
    const float qscale = 0.08838834764831845f;

#pragma unroll
    for (int i = 0; i < 8; i++) {
        int idx = i * 256 + tid;
        int row = idx >> 5;
        int c4  = (idx & 31) << 2;
        float4 v = *(const float4*)(Qg + row * HD + c4);
        Qs[(c4 + 0) * 64 + row] = v.x * qscale;
        Qs[(c4 + 1) * 64 + row] = v.y * qscale;
        Qs[(c4 + 2) * 64 + row] = v.z * qscale;
        Qs[(c4 + 3) * 64 + row] = v.w * qscale;
    }

    const int ty = tid >> 4, tx = tid & 15;
    const int r0 = ty * 4, c0 = tx * 4;

    float o[4][8];
#pragma unroll
    for (int i = 0; i < 4; i++)
#pragma unroll
        for (int j = 0; j < 8; j++) o[i][j] = 0.f;
    float mstate[4] = {-1e30f, -1e30f, -1e30f, -1e30f};
    float lstate[4] = {0.f, 0.f, 0.f, 0.f};

    for (int kt = 0; kt <= qt; kt++) {
        const float* Kg = g_k + ((size_t)bh * SEQ + kt * 64) * HD;
        const float* Vg = g_v + ((size_t)bh * SEQ + kt * 64) * HD;

        __syncthreads();
#pragma unroll
        for (int i = 0; i < 8; i++) {
            int idx = i * 256 + tid;
            int row = idx >> 5;
            int c4  = (idx & 31) << 2;
            float4 kv = *(const float4*)(Kg + row * HD + c4);
            Ks[(c4 + 0) * 64 + row] = kv.x;
            Ks[(c4 + 1) * 64 + row] = kv.y;
            Ks[(c4 + 2) * 64 + row] = kv.z;
            Ks[(c4 + 3) * 64 + row] = kv.w;
            float4 vv = *(const float4*)(Vg + row * HD + c4);
            *(float4*)&Vs[row * 128 + c4] = vv;
        }
        __syncthreads();

        float s[4][4];
#pragma unroll
        for (int i = 0; i < 4; i++)
#pragma unroll
            for (int j = 0; j < 4; j++) s[i][j] = 0.f;
#pragma unroll 4
        for (int d = 0; d < 128; d++) {
            float4 a = *(const float4*)&Qs[d * 64 + r0];
            float4 b = *(const float4*)&Ks[d * 64 + c0];
            float av[4] = {a.x, a.y, a.z, a.w};
            float bv[4] = {b.x, b.y, b.z, b.w};
#pragma unroll
            for (int i = 0; i < 4; i++)
#pragma unroll
                for (int j = 0; j < 4; j++)
                    s[i][j] = fmaf(av[i], bv[j], s[i][j]);
        }

        if (kt == qt) {
#pragma unroll
            for (int i = 0; i < 4; i++)
#pragma unroll
                for (int j = 0; j < 4; j++)
                    if (c0 + j > r0 + i) s[i][j] = -1e30f;
        }

#pragma unroll
        for (int i = 0; i < 4; i++) {
            float mx = s[i][0];
            mx = fmaxf(mx, s[i][1]);
            mx = fmaxf(mx, s[i][2]);
            mx = fmaxf(mx, s[i][3]);
#pragma unroll
            for (int off = 8; off >= 1; off >>= 1)
                mx = fmaxf(mx, __shfl_xor_sync(0xffffffffu, mx, off, 16));
            float mnew = fmaxf(mstate[i], mx);
            float corr = __expf(mstate[i] - mnew);
            float p0 = __expf(s[i][0] - mnew);
            float p1 = __expf(s[i][1] - mnew);
            float p2 = __expf(s[i][2] - mnew);
            float p3 = __expf(s[i][3] - mnew);
            float rs = p0 + p1 + p2 + p3;
#pragma unroll
            for (int off = 8; off >= 1; off >>= 1)
                rs += __shfl_xor_sync(0xffffffffu, rs, off, 16);
            lstate[i] = lstate[i] * corr + rs;
            mstate[i] = mnew;
#pragma unroll
            for (int j = 0; j < 8; j++) o[i][j] *= corr;
            Ps[(c0 + 0) * 64 + r0 + i] = p0;
            Ps[(c0 + 1) * 64 + r0 + i] = p1;
            Ps[(c0 + 2) * 64 + r0 + i] = p2;
            Ps[(c0 + 3) * 64 + r0 + i] = p3;
        }
        __syncthreads();

#pragma unroll 4
        for (int c = 0; c < 64; c++) {
            float4 a  = *(const float4*)&Ps[c * 64 + r0];
            float4 b0 = *(const float4*)&Vs[c * 128 + tx * 8];
            float4 b1 = *(const float4*)&Vs[c * 128 + tx * 8 + 4];
            float av[4] = {a.x, a.y, a.z, a.w};
            float bv[8] = {b0.x, b0.y, b0.z, b0.w, b1.x, b1.y, b1.z, b1.w};
#pragma unroll
            for (int i = 0; i < 4; i++)
#pragma unroll
                for (int j = 0; j < 8; j++)
                    o[i][j] = fmaf(av[i], bv[j], o[i][j]);
        }
    }

    int b = bh >> 4, h = bh & 15;
#pragma unroll
    for (int i = 0; i < 4; i++) {
        float inv = 1.f / lstate[i];
        int srow = qbase + r0 + i;
        float* p = g_att + ((size_t)(b * SEQ + srow) * NH + h) * HD + tx * 8;
        float4 v0 = make_float4(o[i][0] * inv, o[i][1] * inv,
                                o[i][2] * inv, o[i][3] * inv);
        float4 v1 = make_float4(o[i][4] * inv, o[i][5] * inv,
                                o[i][6] * inv, o[i][7] * inv);
        *(float4*)p       = v0;
        *(float4*)(p + 4) = v1;
    }
}

// ---------------------------------------------------------------------------
// Launcher
// ---------------------------------------------------------------------------
extern "C" void kernel_launch(void* const* d_in, const int* in_sizes, int n_in,
                              void* d_out, int out_size)
{
    (void)in_sizes; (void)n_in; (void)out_size;
    const float* X    = (const float*)d_in[0];
    const float* cosp = (const float*)d_in[1];
    const float* sinp = (const float*)d_in[2];
    const float* Wq   = (const float*)d_in[3];
    const float* Wk   = (const float*)d_in[4];
    const float* Wv   = (const float*)d_in[5];
    const float* Wo   = (const float*)d_in[6];
    float* out = (float*)d_out;

    float *q, *k, *v, *att;
    __nv_bfloat16 *xh, *xl, *ath, *atl, *wh, *wl;
    cudaGetSymbolAddress((void**)&q,   g_q);
    cudaGetSymbolAddress((void**)&k,   g_k);
    cudaGetSymbolAddress((void**)&v,   g_v);
    cudaGetSymbolAddress((void**)&att, g_att);
    cudaGetSymbolAddress((void**)&xh,  g_xh);
    cudaGetSymbolAddress((void**)&xl,  g_xl);
    cudaGetSymbolAddress((void**)&ath, g_ath);
    cudaGetSymbolAddress((void**)&atl, g_atl);
    cudaGetSymbolAddress((void**)&wh,  g_wh);
    cudaGetSymbolAddress((void**)&wl,  g_wl);

    const int GEMM_SMEM = 3 * 32768;   // 98304
    cudaFuncSetAttribute(gemm_bf16<0>,
                         cudaFuncAttributeMaxDynamicSharedMemorySize, GEMM_SMEM);
    cudaFuncSetAttribute(gemm_bf16<1>,
                         cudaFuncAttributeMaxDynamicSharedMemorySize, GEMM_SMEM);
    cudaFuncSetAttribute(attn_kernel,
                         cudaFuncAttributeMaxDynamicSharedMemorySize, 114688);

    // 1) split X; transpose+split weights
    split_kernel<<<(MTOT * EMB / 4) / 256, 256>>>(X, xh, xl);
    wsplit_kernel<<<dim3(EMB / 32, EMB / 32, 4), dim3(32, 8)>>>(Wq, Wk, Wv, Wo);

    // 2) QKV projections (bf16 3-term mma.sync)
    dim3 gg(EMB / 128, MTOT / 128);   // (16, 32)
    gemm_bf16<1><<<gg, 256, GEMM_SMEM>>>(xh, xl,
        wh + 0 * (size_t)EMB * EMB, wl + 0 * (size_t)EMB * EMB, q);
    gemm_bf16<1><<<gg, 256, GEMM_SMEM>>>(xh, xl,
        wh + 1 * (size_t)EMB * EMB, wl + 1 * (size_t)EMB * EMB, k);
    gemm_bf16<1><<<gg, 256, GEMM_SMEM>>>(xh, xl,
        wh + 2 * (size_t)EMB * EMB, wl + 2 * (size_t)EMB * EMB, v);

    // 3) RoPE
    rope_kernel<<<(BATCHN * NH * SEQ * 64) / 256, 256>>>(cosp, sinp);

    // 4) causal attention (fp32)
    attn_kernel<<<dim3(32, 32), 256, 114688>>>();

    // 5) split attention output, then O projection
    split_kernel<<<(MTOT * EMB / 4) / 256, 256>>>(att, ath, atl);
    gemm_bf16<0><<<gg, 256, GEMM_SMEM>>>(ath, atl,
        wh + 3 * (size_t)EMB * EMB, wl + 3 * (size_t)EMB * EMB, out);
}

// round 6
// speedup vs baseline: 2.1160x; 1.5836x over previous
#include <cuda_runtime.h>
#include <cuda_bf16.h>
#include <math.h>
#include <cstdint>

// Problem constants
#define BATCHN 2
#define SEQ    2048
#define EMB    2048
#define NH     16
#define HD     128
#define MTOT   (BATCHN * SEQ)   // 4096
#define BK     32
#define KITERS (EMB / BK)       // 64

typedef __nv_bfloat16 bf16;

// ---------------------------------------------------------------------------
// Scratch (static device globals: allocation-free)
// ---------------------------------------------------------------------------
__device__ float g_q[BATCHN * NH * SEQ * HD];    // fp32 q pre-rope [B,H,S,D]
__device__ float g_k[BATCHN * NH * SEQ * HD];    // fp32 k pre-rope
__device__ bf16 g_xh[MTOT * EMB];                // X split hi
__device__ bf16 g_xl[MTOT * EMB];                // X split lo
__device__ bf16 g_qh[BATCHN * NH * SEQ * HD];    // roped+scaled q hi
__device__ bf16 g_ql[BATCHN * NH * SEQ * HD];
__device__ bf16 g_kh[BATCHN * NH * SEQ * HD];    // roped k hi
__device__ bf16 g_kl[BATCHN * NH * SEQ * HD];
__device__ bf16 g_vh[BATCHN * NH * SEQ * HD];    // v hi (gemm direct)
__device__ bf16 g_vl[BATCHN * NH * SEQ * HD];
__device__ bf16 g_ath[MTOT * EMB];               // attention out hi [B,S,H*D]
__device__ bf16 g_atl[MTOT * EMB];
__device__ bf16 g_wh[4 * EMB * EMB];             // W^T split hi, [n][k]
__device__ bf16 g_wl[4 * EMB * EMB];

// ---------------------------------------------------------------------------
// Helpers
// ---------------------------------------------------------------------------
__device__ __forceinline__ uint32_t smem_u32(const void* p) {
    uint32_t a;
    asm("{ .reg .u64 t; cvta.to.shared.u64 t, %1; cvt.u32.u64 %0, t; }"
        : "=r"(a) : "l"(p));
    return a;
}

__device__ __forceinline__ void ldm_x4(uint32_t& r0, uint32_t& r1,
                                       uint32_t& r2, uint32_t& r3, uint32_t a) {
    asm volatile("ldmatrix.sync.aligned.m8n8.x4.shared.b16 {%0,%1,%2,%3}, [%4];"
                 : "=r"(r0), "=r"(r1), "=r"(r2), "=r"(r3) : "r"(a));
}

__device__ __forceinline__ void ldm_x4t(uint32_t& r0, uint32_t& r1,
                                        uint32_t& r2, uint32_t& r3, uint32_t a) {
    asm volatile("ldmatrix.sync.aligned.m8n8.x4.trans.shared.b16 {%0,%1,%2,%3}, [%4];"
                 : "=r"(r0), "=r"(r1), "=r"(r2), "=r"(r3) : "r"(a));
}

__device__ __forceinline__ void mma_bf16(float* c, uint32_t a0, uint32_t a1,
                                         uint32_t a2, uint32_t a3,
                                         uint32_t b0, uint32_t b1) {
    asm volatile("mma.sync.aligned.m16n8k16.row.col.f32.bf16.bf16.f32 "
                 "{%0,%1,%2,%3}, {%4,%5,%6,%7}, {%8,%9}, {%0,%1,%2,%3};"
                 : "+f"(c[0]), "+f"(c[1]), "+f"(c[2]), "+f"(c[3])
                 : "r"(a0), "r"(a1), "r"(a2), "r"(a3), "r"(b0), "r"(b1));
}

#define CP_ASYNC16(dst, src) \
    asm volatile("cp.async.cg.shared.global [%0], [%1], 16;" \
                 :: "r"(dst), "l"(src) : "memory")
#define CP_COMMIT() asm volatile("cp.async.commit_group;" ::: "memory")

// split (x,y) fp32 -> packed bf16x2 hi (returned) and lo (out-param)
__device__ __forceinline__ uint32_t packsplit(float x, float y, uint32_t& lo) {
    __nv_bfloat162 h = __floats2bfloat162_rn(x, y);
    float rx = x - __bfloat162float(__low2bfloat16(h));
    float ry = y - __bfloat162float(__high2bfloat16(h));
    __nv_bfloat162 l = __floats2bfloat162_rn(rx, ry);
    uint32_t hu, lu;
    memcpy(&hu, &h, 4); memcpy(&lu, &l, 4);
    lo = lu;
    return hu;
}

// ---------------------------------------------------------------------------
// Split fp32 -> bf16 hi + bf16 lo (elementwise)
// ---------------------------------------------------------------------------
__global__ void split_kernel(const float* __restrict__ src,
                             bf16* __restrict__ dh, bf16* __restrict__ dl)
{
    int i = blockIdx.x * blockDim.x + threadIdx.x;
    float4 v = ((const float4*)src)[i];
    uint32_t l0, l1;
    uint32_t h0 = packsplit(v.x, v.y, l0);
    uint32_t h1 = packsplit(v.z, v.w, l1);
    ((uint32_t*)dh)[2 * i] = h0; ((uint32_t*)dh)[2 * i + 1] = h1;
    ((uint32_t*)dl)[2 * i] = l0; ((uint32_t*)dl)[2 * i + 1] = l1;
}

// ---------------------------------------------------------------------------
// Transpose + split weights: g_wh/g_wl[z][n*EMB + k] = split(W_z[k*EMB + n])
// ---------------------------------------------------------------------------
__global__ void wsplit_kernel(const float* __restrict__ Wq,
                              const float* __restrict__ Wk,
                              const float* __restrict__ Wv,
                              const float* __restrict__ Wo)
{
    __shared__ float t[32][33];
    const int z = blockIdx.z;
    const float* W = (z == 0) ? Wq : (z == 1) ? Wk : (z == 2) ? Wv : Wo;
    bf16* Oh = g_wh + (size_t)z * EMB * EMB;
    bf16* Ol = g_wl + (size_t)z * EMB * EMB;

    int x  = blockIdx.x * 32 + threadIdx.x;
    int y0 = blockIdx.y * 32;
#pragma unroll
    for (int j = 0; j < 32; j += 8)
        t[threadIdx.y + j][threadIdx.x] = W[(size_t)(y0 + threadIdx.y + j) * EMB + x];
    __syncthreads();
    int ox = y0 + threadIdx.x;
#pragma unroll
    for (int j = 0; j < 32; j += 8) {
        int oy = blockIdx.x * 32 + threadIdx.y + j;
        float val = t[threadIdx.x][threadIdx.y + j];
        bf16 h = __float2bfloat16(val);
        bf16 l = __float2bfloat16(val - __bfloat162float(h));
        Oh[(size_t)oy * EMB + ox] = h;
        Ol[(size_t)oy * EMB + ox] = l;
    }
}

// ---------------------------------------------------------------------------
// bf16 3-term GEMM (proven in round 4).
// MODE 0: fp32 row-major C. MODE 1: fp32 [B,H,S,D]. MODE 2: bf16 hi/lo [B,H,S,D].
// ---------------------------------------------------------------------------
template <int MODE>
__global__ __launch_bounds__(256)
void gemm_bf16(const bf16* __restrict__ Ah, const bf16* __restrict__ Al,
               const bf16* __restrict__ Bh, const bf16* __restrict__ Bl,
               float* __restrict__ C, bf16* __restrict__ Ch, bf16* __restrict__ Cl)
{
    extern __shared__ char smem[];
    const uint32_t sa = smem_u32(smem);
    const int tid  = threadIdx.x;
    const int lane = tid & 31;
    const int wid  = tid >> 5;
    const int m0 = blockIdx.y * 128;
    const int n0 = blockIdx.x * 128;

    const int r    = tid >> 1;
    const int half = tid & 1;
    const bf16* agm = (half ? Al : Ah) + (size_t)(m0 + r) * EMB;
    const bf16* bgm = (half ? Bl : Bh) + (size_t)(n0 + r) * EMB;
    const uint32_t swr    = (uint32_t)((r & 7) << 4);
    const uint32_t ainner = (uint32_t)(half * 64);

    auto issue = [&](int it, int stage) {
        const int k0 = it * BK;
        const uint32_t abase = sa + stage * 32768 + r * 128;
        const uint32_t bbase = abase + 16384;
#pragma unroll
        for (int c = 0; c < 4; c++) {
            uint32_t sw = (ainner + c * 16) ^ swr;
            CP_ASYNC16(abase + sw, agm + k0 + c * 8);
            CP_ASYNC16(bbase + sw, bgm + k0 + c * 8);
        }
    };

    const int wm = (wid & 1) * 64;
    const int wn = (wid >> 1) * 32;
    const int arl = (lane & 7) + ((lane >> 3) & 1) * 8;
    const int koa = (lane >> 4) * 16;
    const int brl = ((lane >> 4) & 1) * 8 + (lane & 7);
    const int kob = ((lane >> 3) & 1) * 16;

    float acc[4][4][4];
#pragma unroll
    for (int mt = 0; mt < 4; mt++)
#pragma unroll
        for (int nt = 0; nt < 4; nt++)
#pragma unroll
            for (int e = 0; e < 4; e++) acc[mt][nt][e] = 0.f;

    issue(0, 0); CP_COMMIT();
    issue(1, 1); CP_COMMIT();

#pragma unroll 1
    for (int it = 0; it < KITERS; it++) {
        if (it + 2 < KITERS) issue(it + 2, (it + 2) % 3);
        CP_COMMIT();
        asm volatile("cp.async.wait_group 2;" ::: "memory");
        __syncthreads();

        const uint32_t ab = sa + (it % 3) * 32768;
        const uint32_t bb = ab + 16384;
#pragma unroll
        for (int s = 0; s < 2; s++) {
            uint32_t ah[4][4], al4[4][4], bhf[4][2], blf[4][2];
#pragma unroll
            for (int mt = 0; mt < 4; mt++) {
                const int row = wm + mt * 16 + arl;
                const uint32_t sw = (uint32_t)((row & 7) << 4);
                const uint32_t base = ab + row * 128;
                const uint32_t ih = (uint32_t)(s * 32 + koa);
                ldm_x4(ah[mt][0], ah[mt][1], ah[mt][2], ah[mt][3], base + (ih ^ sw));
                ldm_x4(al4[mt][0], al4[mt][1], al4[mt][2], al4[mt][3],
                       base + ((ih + 64) ^ sw));
            }
#pragma unroll
            for (int np = 0; np < 2; np++) {
                const int row = wn + np * 16 + brl;
                const uint32_t sw = (uint32_t)((row & 7) << 4);
                const uint32_t base = bb + row * 128;
                const uint32_t ih = (uint32_t)(s * 32 + kob);
                uint32_t h0, h1, h2, h3, l0, l1, l2, l3;
                ldm_x4(h0, h1, h2, h3, base + (ih ^ sw));
                ldm_x4(l0, l1, l2, l3, base + ((ih + 64) ^ sw));
                bhf[np * 2][0] = h0; bhf[np * 2][1] = h1;
                bhf[np * 2 + 1][0] = h2; bhf[np * 2 + 1][1] = h3;
                blf[np * 2][0] = l0; blf[np * 2][1] = l1;
                blf[np * 2 + 1][0] = l2; blf[np * 2 + 1][1] = l3;
            }
#pragma unroll
            for (int mt = 0; mt < 4; mt++)
#pragma unroll
                for (int nt = 0; nt < 4; nt++) {
                    float* c = acc[mt][nt];
                    mma_bf16(c, ah[mt][0], ah[mt][1], ah[mt][2], ah[mt][3],
                             bhf[nt][0], bhf[nt][1]);
                    mma_bf16(c, ah[mt][0], ah[mt][1], ah[mt][2], ah[mt][3],
                             blf[nt][0], blf[nt][1]);
                    mma_bf16(c, al4[mt][0], al4[mt][1], al4[mt][2], al4[mt][3],
                             bhf[nt][0], bhf[nt][1]);
                }
        }
        __syncthreads();
    }

    const int g = lane >> 2, tig = lane & 3;
#pragma unroll
    for (int mt = 0; mt < 4; mt++) {
        const int m = m0 + wm + mt * 16 + g;
#pragma unroll
        for (int nt = 0; nt < 4; nt++) {
            const int col = wn + nt * 8 + 2 * tig;
            float2 v0 = make_float2(acc[mt][nt][0], acc[mt][nt][1]);
            float2 v1 = make_float2(acc[mt][nt][2], acc[mt][nt][3]);
            if (MODE == 0) {
                float* p = C + (size_t)m * EMB + n0 + col;
                *(float2*)p = v0;
                *(float2*)(p + (size_t)8 * EMB) = v1;
            } else if (MODE == 1) {
                const int b = m >> 11, si = m & 2047, h = n0 >> 7;
                float* p = C + ((size_t)(b * NH + h) * SEQ + si) * HD + col;
                *(float2*)p = v0;
                *(float2*)(p + 8 * HD) = v1;
            } else {
                const int b = m >> 11, si = m & 2047, h = n0 >> 7;
                size_t base = ((size_t)(b * NH + h) * SEQ + si) * HD + col;
                uint32_t lo0, lo1;
                uint32_t hi0 = packsplit(v0.x, v0.y, lo0);
                uint32_t hi1 = packsplit(v1.x, v1.y, lo1);
                *(uint32_t*)(Ch + base) = hi0;
                *(uint32_t*)(Cl + base) = lo0;
                *(uint32_t*)(Ch + base + 8 * HD) = hi1;
                *(uint32_t*)(Cl + base + 8 * HD) = lo1;
            }
        }
    }
}

// ---------------------------------------------------------------------------
// RoPE + split: read fp32 g_q/g_k, write bf16 hi/lo (q scaled by 1/sqrt(HD)).
// ---------------------------------------------------------------------------
__global__ void rope_split_kernel(const float* __restrict__ cosp,
                                  const float* __restrict__ sinp)
{
    int gid = blockIdx.x * blockDim.x + threadIdx.x;
    int d  = gid & 63;
    int s  = (gid >> 6) & (SEQ - 1);
    int bh = gid >> 17;
    int b  = bh >> 4;
    const float qscale = 0.08838834764831845f;

    int co = (b * SEQ + s) * HD;
    float c1 = cosp[co + d],      s1 = sinp[co + d];
    float c2 = cosp[co + d + 64], s2 = sinp[co + d + 64];

    size_t qo = ((size_t)bh * SEQ + s) * HD + d;
    float x1 = g_q[qo], x2 = g_q[qo + 64];
    float q1 = (x1 * c1 - x2 * s1) * qscale;
    float q2 = (x2 * c2 + x1 * s2) * qscale;
    bf16 h;
    h = __float2bfloat16(q1); g_qh[qo] = h;
    g_ql[qo] = __float2bfloat16(q1 - __bfloat162float(h));
    h = __float2bfloat16(q2); g_qh[qo + 64] = h;
    g_ql[qo + 64] = __float2bfloat16(q2 - __bfloat162float(h));

    x1 = g_k[qo]; x2 = g_k[qo + 64];
    float k1 = x1 * c1 - x2 * s1;
    float k2 = x2 * c2 + x1 * s2;
    h = __float2bfloat16(k1); g_kh[qo] = h;
    g_kl[qo] = __float2bfloat16(k1 - __bfloat162float(h));
    h = __float2bfloat16(k2); g_kh[qo + 64] = h;
    g_kl[qo + 64] = __float2bfloat16(k2 - __bfloat162float(h));
}

// ---------------------------------------------------------------------------
// Tensor-core causal flash attention (3-term bf16), 96KB smem.
// BM=128 (8 warps x m16), BN=32, D=128.
// smem: 3 stages x 32KB; stage = Kh(8K) | Kl(8K) | Vh(8K) | Vl(8K).
// Q staged through stages 0-1 during prologue, then lives in registers.
// Output written as bf16 hi/lo into g_ath/g_atl [B,S,H*D].
// ---------------------------------------------------------------------------
__global__ __launch_bounds__(256)
void attn_kernel()
{
    extern __shared__ char smem[];
    const uint32_t sa = smem_u32(smem);
    const int tid = threadIdx.x, lane = tid & 31, wid = tid >> 5;
    const int qt = blockIdx.x, bh = blockIdx.y;
    const int qbase = qt * 128;
    const int nk = 4 * (qt + 1);          // 32-col tiles
    const int wm = wid * 16;

    // ---- Load Q (hi/lo) into stage 0+1 smem (64KB), 256B rows, swizzled
    {
        const int u = tid >> 7;          // 0 hi, 1 lo
        const int row = tid & 127;
        const bf16* src = (u ? g_ql : g_qh) + ((size_t)bh * SEQ + qbase + row) * HD;
        const uint32_t dst = sa + u * 32768 + row * 256;
        const uint32_t swr = (uint32_t)((row & 7) << 4);
#pragma unroll
        for (int c = 0; c < 16; c++)
            CP_ASYNC16(dst + ((c * 16) ^ swr), src + c * 8);
        CP_COMMIT();
    }
    asm volatile("cp.async.wait_group 0;" ::: "memory");
    __syncthreads();

    // ---- Extract Q fragments to registers (m16k16 x 8 kt, hi+lo)
    uint32_t qh[8][4], ql[8][4];
    {
        const int arow = wm + (lane & 7) + ((lane >> 3) & 1) * 8;
        const uint32_t swr = (uint32_t)((arow & 7) << 4);
#pragma unroll
        for (int kt = 0; kt < 8; kt++) {
            const uint32_t c = (uint32_t)(kt * 2 + (lane >> 4));
            const uint32_t off = arow * 256 + ((c * 16) ^ swr);
            ldm_x4(qh[kt][0], qh[kt][1], qh[kt][2], qh[kt][3], sa + off);
            ldm_x4(ql[kt][0], ql[kt][1], ql[kt][2], ql[kt][3], sa + 32768 + off);
        }
    }
    __syncthreads();   // stages 0-1 free for KV reuse

    // ---- KV loader: unit u4 = Kh/Kl/Vh/Vl (8KB each: 32 rows x 256B)
    const int u4    = tid >> 6;          // 0 Kh 1 Kl 2 Vh 3 Vl
    const int krow  = (tid & 63) >> 1;   // 0..31
    const int halfc = tid & 1;           // which 128B of the row
    const bf16* kvsrc =
        (u4 == 0 ? g_kh : u4 == 1 ? g_kl : u4 == 2 ? g_vh : g_vl) +
        (size_t)bh * SEQ * HD;
    const uint32_t kswr = (uint32_t)((krow & 7) << 4);

    auto issueKV = [&](int kt, int st) {
        const bf16* s = kvsrc + (size_t)(kt * 32 + krow) * HD + halfc * 64;
        const uint32_t dst = sa + st * 32768 + u4 * 8192 + krow * 256;
        const uint32_t cb = (uint32_t)(halfc * 128);
#pragma unroll
        for (int c = 0; c < 8; c++)
            CP_ASYNC16(dst + ((cb + c * 16) ^ kswr), s + c * 8);
    };

    issueKV(0, 0); CP_COMMIT();
    issueKV(1, 1); CP_COMMIT();

    float o[16][4];
#pragma unroll
    for (int nd = 0; nd < 16; nd++)
#pragma unroll
        for (int e = 0; e < 4; e++) o[nd][e] = 0.f;
    float m1 = -1e30f, m2 = -1e30f, l1 = 0.f, l2 = 0.f;

    const int brl  = ((lane >> 4) & 1) * 8 + (lane & 7);
    const int kobc = (lane >> 3) & 1;

#pragma unroll 1
    for (int kt = 0; kt < nk; kt++) {
        if (kt < nk - 1) asm volatile("cp.async.wait_group 1;" ::: "memory");
        else            asm volatile("cp.async.wait_group 0;" ::: "memory");
        __syncthreads();
        if (kt + 2 < nk) issueKV(kt + 2, (kt + 2) % 3);
        CP_COMMIT();

        const int rel = kt * 32 - qbase;      // col offset rel to block rows
        if (rel > wm + 15) continue;          // warp-tile fully masked

        const uint32_t kb = sa + (kt % 3) * 32768;

        // ---- S = Q . K^T  (3-term), 32 cols -> sacc[4][4]
        float sacc[4][4];
#pragma unroll
        for (int nt = 0; nt < 4; nt++)
#pragma unroll
            for (int e = 0; e < 4; e++) sacc[nt][e] = 0.f;

#pragma unroll
        for (int kt16 = 0; kt16 < 8; kt16++) {
#pragma unroll
            for (int np = 0; np < 2; np++) {
                const int row = np * 16 + brl;
                const uint32_t sw = (uint32_t)((row & 7) << 4);
                const uint32_t off =
                    row * 256 + (((uint32_t)(kt16 * 2 + kobc) * 16) ^ sw);
                uint32_t h0, h1, h2, h3, e0, e1, e2, e3;
                ldm_x4(h0, h1, h2, h3, kb + off);
                ldm_x4(e0, e1, e2, e3, kb + 8192 + off);
                float* s0 = sacc[2 * np];
                float* s1 = sacc[2 * np + 1];
                mma_bf16(s0, qh[kt16][0], qh[kt16][1], qh[kt16][2], qh[kt16][3], h0, h1);
                mma_bf16(s0, qh[kt16][0], qh[kt16][1], qh[kt16][2], qh[kt16][3], e0, e1);
                mma_bf16(s0, ql[kt16][0], ql[kt16][1], ql[kt16][2], ql[kt16][3], h0, h1);
                mma_bf16(s1, qh[kt16][0], qh[kt16][1], qh[kt16][2], qh[kt16][3], h2, h3);
                mma_bf16(s1, qh[kt16][0], qh[kt16][1], qh[kt16][2], qh[kt16][3], e2, e3);
                mma_bf16(s1, ql[kt16][0], ql[kt16][1], ql[kt16][2], ql[kt16][3], h2, h3);
            }
        }

        // ---- causal mask (tiles overlapping the diagonal)
        if (rel + 31 > wm) {
            const int r1 = wm + (lane >> 2), r2 = r1 + 8;
#pragma unroll
            for (int nt = 0; nt < 4; nt++) {
                const int c0 = rel + nt * 8 + (lane & 3) * 2;
                if (c0     > r1) sacc[nt][0] = -1e30f;
                if (c0 + 1 > r1) sacc[nt][1] = -1e30f;
                if (c0     > r2) sacc[nt][2] = -1e30f;
                if (c0 + 1 > r2) sacc[nt][3] = -1e30f;
            }
        }

        // ---- online softmax (rows r1, r2; quad-lane reduce)
        float rmx1 = -1e30f, rmx2 = -1e30f;
#pragma unroll
        for (int nt = 0; nt < 4; nt++) {
            rmx1 = fmaxf(rmx1, fmaxf(sacc[nt][0], sacc[nt][1]));
            rmx2 = fmaxf(rmx2, fmaxf(sacc[nt][2], sacc[nt][3]));
        }
        rmx1 = fmaxf(rmx1, __shfl_xor_sync(0xffffffffu, rmx1, 1));
        rmx1 = fmaxf(rmx1, __shfl_xor_sync(0xffffffffu, rmx1, 2));
        rmx2 = fmaxf(rmx2, __shfl_xor_sync(0xffffffffu, rmx2, 1));
        rmx2 = fmaxf(rmx2, __shfl_xor_sync(0xffffffffu, rmx2, 2));

        const float nm1 = fmaxf(m1, rmx1), nm2 = fmaxf(m2, rmx2);
        const float corr1 = __expf(m1 - nm1), corr2 = __expf(m2 - nm2);
        m1 = nm1; m2 = nm2;

        float ps1 = 0.f, ps2 = 0.f;
#pragma unroll
        for (int nt = 0; nt < 4; nt++) {
            sacc[nt][0] = __expf(sacc[nt][0] - m1);
            sacc[nt][1] = __expf(sacc[nt][1] - m1);
            sacc[nt][2] = __expf(sacc[nt][2] - m2);
            sacc[nt][3] = __expf(sacc[nt][3] - m2);
            ps1 += sacc[nt][0] + sacc[nt][1];
            ps2 += sacc[nt][2] + sacc[nt][3];
        }
        ps1 += __shfl_xor_sync(0xffffffffu, ps1, 1);
        ps1 += __shfl_xor_sync(0xffffffffu, ps1, 2);
        ps2 += __shfl_xor_sync(0xffffffffu, ps2, 1);
        ps2 += __shfl_xor_sync(0xffffffffu, ps2, 2);
        l1 = l1 * corr1 + ps1;
        l2 = l2 * corr2 + ps2;

#pragma unroll
        for (int nd = 0; nd < 16; nd++) {
            o[nd][0] *= corr1; o[nd][1] *= corr1;
            o[nd][2] *= corr2; o[nd][3] *= corr2;
        }

        // ---- P fragments (C-layout -> A-layout), hi/lo split (k range 32)
        uint32_t pa[2][4], pl[2][4];
#pragma unroll
        for (int t = 0; t < 2; t++) {
            pa[t][0] = packsplit(sacc[2 * t][0],     sacc[2 * t][1],     pl[t][0]);
            pa[t][1] = packsplit(sacc[2 * t][2],     sacc[2 * t][3],     pl[t][1]);
            pa[t][2] = packsplit(sacc[2 * t + 1][0], sacc[2 * t + 1][1], pl[t][2]);
            pa[t][3] = packsplit(sacc[2 * t + 1][2], sacc[2 * t + 1][3], pl[t][3]);
        }

        // ---- O += P . V (3-term), V b-frags via ldmatrix.trans
        const int kk15 = lane & 15;
        const int nhi  = (lane >> 4) * 8;
#pragma unroll
        for (int nd2 = 0; nd2 < 8; nd2++) {
#pragma unroll
            for (int t = 0; t < 2; t++) {
                const int kk = t * 16 + kk15;
                const int nn = nd2 * 16 + nhi;
                const uint32_t off =
                    kk * 256 + ((((uint32_t)(nn >> 3)) * 16) ^ ((uint32_t)((kk & 7) << 4)));
                uint32_t vh0, vh1, vh2, vh3, vl0, vl1, vl2, vl3;
                ldm_x4t(vh0, vh1, vh2, vh3, kb + 16384 + off);
                ldm_x4t(vl0, vl1, vl2, vl3, kb + 24576 + off);
                float* o0 = o[2 * nd2];
                float* o1 = o[2 * nd2 + 1];
                mma_bf16(o0, pa[t][0], pa[t][1], pa[t][2], pa[t][3], vh0, vh1);
                mma_bf16(o0, pa[t][0], pa[t][1], pa[t][2], pa[t][3], vl0, vl1);
                mma_bf16(o0, pl[t][0], pl[t][1], pl[t][2], pl[t][3], vh0, vh1);
                mma_bf16(o1, pa[t][0], pa[t][1], pa[t][2], pa[t][3], vh2, vh3);
                mma_bf16(o1, pa[t][0], pa[t][1], pa[t][2], pa[t][3], vl2, vl3);
                mma_bf16(o1, pl[t][0], pl[t][1], pl[t][2], pl[t][3], vh2, vh3);
            }
        }
    }

    // ---- epilogue: normalize, split, store bf16 hi/lo [B,S,H*D]
    const float inv1 = 1.f / l1, inv2 = 1.f / l2;
    const int b = bh >> 4, h = bh & 15;
    const int srow1 = qbase + wm + (lane >> 2);
    const size_t base1 = (size_t)(b * SEQ + srow1) * EMB + h * HD;
    const size_t base2 = base1 + (size_t)8 * EMB;
#pragma unroll
    for (int nd = 0; nd < 16; nd++) {
        const int d = nd * 8 + (lane & 3) * 2;
        uint32_t lo;
        uint32_t hi = packsplit(o[nd][0] * inv1, o[nd][1] * inv1, lo);
        *(uint32_t*)(g_ath + base1 + d) = hi;
        *(uint32_t*)(g_atl + base1 + d) = lo;
        hi = packsplit(o[nd][2] * inv2, o[nd][3] * inv2, lo);
        *(uint32_t*)(g_ath + base2 + d) = hi;
        *(uint32_t*)(g_atl + base2 + d) = lo;
    }
}

// ---------------------------------------------------------------------------
// Launcher
// ---------------------------------------------------------------------------
extern "C" void kernel_launch(void* const* d_in, const int* in_sizes, int n_in,
                              void* d_out, int out_size)
{
    (void)in_sizes; (void)n_in; (void)out_size;
    const float* X    = (const float*)d_in[0];
    const float* cosp = (const float*)d_in[1];
    const float* sinp = (const float*)d_in[2];
    const float* Wq   = (const float*)d_in[3];
    const float* Wk   = (const float*)d_in[4];
    const float* Wv   = (const float*)d_in[5];
    const float* Wo   = (const float*)d_in[6];
    float* out = (float*)d_out;

    float *q, *k;
    bf16 *xh, *xl, *ath, *atl, *wh, *wl, *vh, *vl;
    cudaGetSymbolAddress((void**)&q,   g_q);
    cudaGetSymbolAddress((void**)&k,   g_k);
    cudaGetSymbolAddress((void**)&xh,  g_xh);
    cudaGetSymbolAddress((void**)&xl,  g_xl);
    cudaGetSymbolAddress((void**)&ath, g_ath);
    cudaGetSymbolAddress((void**)&atl, g_atl);
    cudaGetSymbolAddress((void**)&wh,  g_wh);
    cudaGetSymbolAddress((void**)&wl,  g_wl);
    cudaGetSymbolAddress((void**)&vh,  g_vh);
    cudaGetSymbolAddress((void**)&vl,  g_vl);

    const int GEMM_SMEM = 3 * 32768;   // 98304 (proven)
    const int ATT_SMEM  = 3 * 32768;   // 98304 (same proven footprint)
    cudaFuncSetAttribute(gemm_bf16<0>,
                         cudaFuncAttributeMaxDynamicSharedMemorySize, GEMM_SMEM);
    cudaFuncSetAttribute(gemm_bf16<1>,
                         cudaFuncAttributeMaxDynamicSharedMemorySize, GEMM_SMEM);
    cudaFuncSetAttribute(gemm_bf16<2>,
                         cudaFuncAttributeMaxDynamicSharedMemorySize, GEMM_SMEM);
    cudaFuncSetAttribute(attn_kernel,
                         cudaFuncAttributeMaxDynamicSharedMemorySize, ATT_SMEM);

    // 1) split X; transpose+split weights
    split_kernel<<<(MTOT * EMB / 4) / 256, 256>>>(X, xh, xl);
    wsplit_kernel<<<dim3(EMB / 32, EMB / 32, 4), dim3(32, 8)>>>(Wq, Wk, Wv, Wo);

    // 2) QKV projections (q,k -> fp32 for rope; v -> bf16 hi/lo direct)
    dim3 gg(EMB / 128, MTOT / 128);   // (16, 32)
    gemm_bf16<1><<<gg, 256, GEMM_SMEM>>>(xh, xl,
        wh + 0 * (size_t)EMB * EMB, wl + 0 * (size_t)EMB * EMB, q, nullptr, nullptr);
    gemm_bf16<1><<<gg, 256, GEMM_SMEM>>>(xh, xl,
        wh + 1 * (size_t)EMB * EMB, wl + 1 * (size_t)EMB * EMB, k, nullptr, nullptr);
    gemm_bf16<2><<<gg, 256, GEMM_SMEM>>>(xh, xl,
        wh + 2 * (size_t)EMB * EMB, wl + 2 * (size_t)EMB * EMB, nullptr, vh, vl);

    // 3) RoPE + split to bf16 hi/lo
    rope_split_kernel<<<(BATCHN * NH * SEQ * 64) / 256, 256>>>(cosp, sinp);

    // 4) tensor-core causal attention -> g_ath/g_atl
    attn_kernel<<<dim3(16, 32), 256, ATT_SMEM>>>();

    // 5) O projection
    gemm_bf16<0><<<gg, 256, GEMM_SMEM>>>(ath, atl,
        wh + 3 * (size_t)EMB * EMB, wl + 3 * (size_t)EMB * EMB, out, nullptr, nullptr);
}

// round 9
// speedup vs baseline: 2.4936x; 1.1784x over previous
#include <cuda_runtime.h>
#include <cuda_bf16.h>
#include <math.h>
#include <cstdint>

// Problem constants
#define BATCHN 2
#define SEQ    2048
#define EMB    2048
#define NH     16
#define HD     128
#define MTOT   (BATCHN * SEQ)   // 4096
#define BK     32
#define KITERS (EMB / BK)       // 64

typedef __nv_bfloat16 bf16;

// ---------------------------------------------------------------------------
// Scratch (static device globals: allocation-free)
// ---------------------------------------------------------------------------
__device__ float g_q[BATCHN * NH * SEQ * HD];    // fp32 q pre-rope [B,H,S,D]
__device__ float g_k[BATCHN * NH * SEQ * HD];    // fp32 k pre-rope
__device__ bf16 g_xh[MTOT * EMB];                // X split hi
__device__ bf16 g_xl[MTOT * EMB];                // X split lo
__device__ bf16 g_qh[BATCHN * NH * SEQ * HD];    // roped+scaled q hi
__device__ bf16 g_ql[BATCHN * NH * SEQ * HD];
__device__ bf16 g_kh[BATCHN * NH * SEQ * HD];    // roped k hi
__device__ bf16 g_kl[BATCHN * NH * SEQ * HD];
__device__ bf16 g_vh[BATCHN * NH * SEQ * HD];    // v hi (gemm direct)
__device__ bf16 g_vl[BATCHN * NH * SEQ * HD];
__device__ bf16 g_ath[MTOT * EMB];               // attention out hi [B,S,H*D]
__device__ bf16 g_atl[MTOT * EMB];
__device__ bf16 g_wh[4 * EMB * EMB];             // W^T split hi, [n][k]
__device__ bf16 g_wl[4 * EMB * EMB];

// ---------------------------------------------------------------------------
// Helpers
// ---------------------------------------------------------------------------
__device__ __forceinline__ uint32_t smem_u32(const void* p) {
    uint32_t a;
    asm("{ .reg .u64 t; cvta.to.shared.u64 t, %1; cvt.u32.u64 %0, t; }"
        : "=r"(a) : "l"(p));
    return a;
}

__device__ __forceinline__ void ldm_x4(uint32_t& r0, uint32_t& r1,
                                       uint32_t& r2, uint32_t& r3, uint32_t a) {
    asm volatile("ldmatrix.sync.aligned.m8n8.x4.shared.b16 {%0,%1,%2,%3}, [%4];"
                 : "=r"(r0), "=r"(r1), "=r"(r2), "=r"(r3) : "r"(a));
}

__device__ __forceinline__ void ldm_x4t(uint32_t& r0, uint32_t& r1,
                                        uint32_t& r2, uint32_t& r3, uint32_t a) {
    asm volatile("ldmatrix.sync.aligned.m8n8.x4.trans.shared.b16 {%0,%1,%2,%3}, [%4];"
                 : "=r"(r0), "=r"(r1), "=r"(r2), "=r"(r3) : "r"(a));
}

__device__ __forceinline__ void mma_bf16(float* c, uint32_t a0, uint32_t a1,
                                         uint32_t a2, uint32_t a3,
                                         uint32_t b0, uint32_t b1) {
    asm volatile("mma.sync.aligned.m16n8k16.row.col.f32.bf16.bf16.f32 "
                 "{%0,%1,%2,%3}, {%4,%5,%6,%7}, {%8,%9}, {%0,%1,%2,%3};"
                 : "+f"(c[0]), "+f"(c[1]), "+f"(c[2]), "+f"(c[3])
                 : "r"(a0), "r"(a1), "r"(a2), "r"(a3), "r"(b0), "r"(b1));
}

#define CP_ASYNC16(dst, src) \
    asm volatile("cp.async.cg.shared.global [%0], [%1], 16;" \
                 :: "r"(dst), "l"(src) : "memory")
#define CP_COMMIT() asm volatile("cp.async.commit_group;" ::: "memory")

// split (x,y) fp32 -> packed bf16x2 hi (returned) and lo (out-param)
__device__ __forceinline__ uint32_t packsplit(float x, float y, uint32_t& lo) {
    __nv_bfloat162 h = __floats2bfloat162_rn(x, y);
    float rx = x - __bfloat162float(__low2bfloat16(h));
    float ry = y - __bfloat162float(__high2bfloat16(h));
    __nv_bfloat162 l = __floats2bfloat162_rn(rx, ry);
    uint32_t hu, lu;
    memcpy(&hu, &h, 4); memcpy(&lu, &l, 4);
    lo = lu;
    return hu;
}

// ---------------------------------------------------------------------------
// Split fp32 -> bf16 hi + bf16 lo (elementwise)
// ---------------------------------------------------------------------------
__global__ void split_kernel(const float* __restrict__ src,
                             bf16* __restrict__ dh, bf16* __restrict__ dl)
{
    int i = blockIdx.x * blockDim.x + threadIdx.x;
    float4 v = ((const float4*)src)[i];
    uint32_t l0, l1;
    uint32_t h0 = packsplit(v.x, v.y, l0);
    uint32_t h1 = packsplit(v.z, v.w, l1);
    ((uint32_t*)dh)[2 * i] = h0; ((uint32_t*)dh)[2 * i + 1] = h1;
    ((uint32_t*)dl)[2 * i] = l0; ((uint32_t*)dl)[2 * i + 1] = l1;
}

// ---------------------------------------------------------------------------
// Transpose + split weights: g_wh/g_wl[z][n*EMB + k] = split(W_z[k*EMB + n])
// ---------------------------------------------------------------------------
__global__ void wsplit_kernel(const float* __restrict__ Wq,
                              const float* __restrict__ Wk,
                              const float* __restrict__ Wv,
                              const float* __restrict__ Wo)
{
    __shared__ float t[32][33];
    const int z = blockIdx.z;
    const float* W = (z == 0) ? Wq : (z == 1) ? Wk : (z == 2) ? Wv : Wo;
    bf16* Oh = g_wh + (size_t)z * EMB * EMB;
    bf16* Ol = g_wl + (size_t)z * EMB * EMB;

    int x  = blockIdx.x * 32 + threadIdx.x;
    int y0 = blockIdx.y * 32;
#pragma unroll
    for (int j = 0; j < 32; j += 8)
        t[threadIdx.y + j][threadIdx.x] = W[(size_t)(y0 + threadIdx.y + j) * EMB + x];
    __syncthreads();
    int ox = y0 + threadIdx.x;
#pragma unroll
    for (int j = 0; j < 32; j += 8) {
        int oy = blockIdx.x * 32 + threadIdx.y + j;
        float val = t[threadIdx.x][threadIdx.y + j];
        bf16 h = __float2bfloat16(val);
        bf16 l = __float2bfloat16(val - __bfloat162float(h));
        Oh[(size_t)oy * EMB + ox] = h;
        Ol[(size_t)oy * EMB + ox] = l;
    }
}

// ---------------------------------------------------------------------------
// bf16 3-term GEMM core. 128x128 tile, BK=32, 2-stage cp.async (64KB smem),
// __launch_bounds__(256,2) for 2 CTAs/SM.
// QKV=1: grid.z in {0,1,2} selects weight z and destination:
//        z=0 -> fp32 g_q [B,H,S,D] (via C); z=1 -> fp32 g_k (via Cl cast);
//        z=2 -> bf16 vh (via Ch) + g_vl.
// QKV=0: single weight (Bh/Bl as passed), fp32 row-major C.
// ---------------------------------------------------------------------------
template <int QKV>
__global__ __launch_bounds__(256, 2)
void gemm_bf16(const bf16* __restrict__ Ah, const bf16* __restrict__ Al,
               const bf16* __restrict__ Bh0, const bf16* __restrict__ Bl0,
               float* __restrict__ C, bf16* __restrict__ Ch, bf16* __restrict__ Cl)
{
    extern __shared__ char smem[];
    const uint32_t sa = smem_u32(smem);
    const int tid  = threadIdx.x;
    const int lane = tid & 31;
    const int wid  = tid >> 5;
    const int m0 = blockIdx.y * 128;
    const int n0 = blockIdx.x * 128;
    const int z  = QKV ? blockIdx.z : 0;

    const bf16* Bh = Bh0 + (size_t)z * EMB * EMB;
    const bf16* Bl = Bl0 + (size_t)z * EMB * EMB;

    const int r    = tid >> 1;
    const int half = tid & 1;
    const bf16* agm = (half ? Al : Ah) + (size_t)(m0 + r) * EMB;
    const bf16* bgm = (half ? Bl : Bh) + (size_t)(n0 + r) * EMB;
    const uint32_t swr    = (uint32_t)((r & 7) << 4);
    const uint32_t ainner = (uint32_t)(half * 64);

    auto issue = [&](int it, int stage) {
        const int k0 = it * BK;
        const uint32_t abase = sa + stage * 32768 + r * 128;
        const uint32_t bbase = abase + 16384;
#pragma unroll
        for (int c = 0; c < 4; c++) {
            uint32_t sw = (ainner + c * 16) ^ swr;
            CP_ASYNC16(abase + sw, agm + k0 + c * 8);
            CP_ASYNC16(bbase + sw, bgm + k0 + c * 8);
        }
    };

    const int wm = (wid & 1) * 64;
    const int wn = (wid >> 1) * 32;
    const int arl = (lane & 7) + ((lane >> 3) & 1) * 8;
    const int koa = (lane >> 4) * 16;
    const int brl = ((lane >> 4) & 1) * 8 + (lane & 7);
    const int kob = ((lane >> 3) & 1) * 16;

    float acc[4][4][4];
#pragma unroll
    for (int mt = 0; mt < 4; mt++)
#pragma unroll
        for (int nt = 0; nt < 4; nt++)
#pragma unroll
            for (int e = 0; e < 4; e++) acc[mt][nt][e] = 0.f;

    issue(0, 0); CP_COMMIT();
    issue(1, 1); CP_COMMIT();

#pragma unroll 1
    for (int it = 0; it < KITERS; it++) {
        asm volatile("cp.async.wait_group 1;" ::: "memory");
        __syncthreads();

        const uint32_t ab = sa + (it & 1) * 32768;
        const uint32_t bb = ab + 16384;
#pragma unroll
        for (int s = 0; s < 2; s++) {
            uint32_t ah[4][4], al4[4][4];
#pragma unroll
            for (int mt = 0; mt < 4; mt++) {
                const int row = wm + mt * 16 + arl;
                const uint32_t sw = (uint32_t)((row & 7) << 4);
                const uint32_t base = ab + row * 128;
                const uint32_t ih = (uint32_t)(s * 32 + koa);
                ldm_x4(ah[mt][0], ah[mt][1], ah[mt][2], ah[mt][3], base + (ih ^ sw));
                ldm_x4(al4[mt][0], al4[mt][1], al4[mt][2], al4[mt][3],
                       base + ((ih + 64) ^ sw));
            }
#pragma unroll
            for (int np = 0; np < 2; np++) {
                const int row = wn + np * 16 + brl;
                const uint32_t sw = (uint32_t)((row & 7) << 4);
                const uint32_t base = bb + row * 128;
                const uint32_t ih = (uint32_t)(s * 32 + kob);
                uint32_t h0, h1, h2, h3, l0, l1, l2, l3;
                ldm_x4(h0, h1, h2, h3, base + (ih ^ sw));
                ldm_x4(l0, l1, l2, l3, base + ((ih + 64) ^ sw));
#pragma unroll
                for (int mt = 0; mt < 4; mt++) {
                    float* c0 = acc[mt][2 * np];
                    float* c1 = acc[mt][2 * np + 1];
                    mma_bf16(c0, ah[mt][0], ah[mt][1], ah[mt][2], ah[mt][3], h0, h1);
                    mma_bf16(c0, ah[mt][0], ah[mt][1], ah[mt][2], ah[mt][3], l0, l1);
                    mma_bf16(c0, al4[mt][0], al4[mt][1], al4[mt][2], al4[mt][3], h0, h1);
                    mma_bf16(c1, ah[mt][0], ah[mt][1], ah[mt][2], ah[mt][3], h2, h3);
                    mma_bf16(c1, ah[mt][0], ah[mt][1], ah[mt][2], ah[mt][3], l2, l3);
                    mma_bf16(c1, al4[mt][0], al4[mt][1], al4[mt][2], al4[mt][3], h2, h3);
                }
            }
        }
        __syncthreads();
        if (it + 2 < KITERS) { issue(it + 2, it & 1); }
        CP_COMMIT();
    }

    // Epilogue
    const int g = lane >> 2, tig = lane & 3;
#pragma unroll
    for (int mt = 0; mt < 4; mt++) {
        const int m = m0 + wm + mt * 16 + g;
#pragma unroll
        for (int nt = 0; nt < 4; nt++) {
            const int col = wn + nt * 8 + 2 * tig;
            float2 v0 = make_float2(acc[mt][nt][0], acc[mt][nt][1]);
            float2 v1 = make_float2(acc[mt][nt][2], acc[mt][nt][3]);
            if (!QKV) {
                float* p = C + (size_t)m * EMB + n0 + col;
                *(float2*)p = v0;
                *(float2*)(p + (size_t)8 * EMB) = v1;
            } else {
                const int b = m >> 11, si = m & 2047, h = n0 >> 7;
                const size_t base = ((size_t)(b * NH + h) * SEQ + si) * HD + col;
                if (z < 2) {
                    float* dst = (z == 0 ? C : (float*)Cl);  // C=g_q, Cl reused=g_k
                    *(float2*)(dst + base) = v0;
                    *(float2*)(dst + base + 8 * HD) = v1;
                } else {
                    uint32_t lo0, lo1;
                    uint32_t hi0 = packsplit(v0.x, v0.y, lo0);
                    uint32_t hi1 = packsplit(v1.x, v1.y, lo1);
                    *(uint32_t*)(Ch + base) = hi0;
                    *(uint32_t*)(Ch + base + 8 * HD) = hi1;
                    *(uint32_t*)(g_vl + base) = lo0;
                    *(uint32_t*)(g_vl + base + 8 * HD) = lo1;
                }
            }
        }
    }
}

// ---------------------------------------------------------------------------
// RoPE + split: read fp32 g_q/g_k, write bf16 hi/lo (q scaled by 1/sqrt(HD)).
// ---------------------------------------------------------------------------
__global__ void rope_split_kernel(const float* __restrict__ cosp,
                                  const float* __restrict__ sinp)
{
    int gid = blockIdx.x * blockDim.x + threadIdx.x;
    int d  = gid & 63;
    int s  = (gid >> 6) & (SEQ - 1);
    int bh = gid >> 17;
    int b  = bh >> 4;
    const float qscale = 0.08838834764831845f;

    int co = (b * SEQ + s) * HD;
    float c1 = cosp[co + d],      s1 = sinp[co + d];
    float c2 = cosp[co + d + 64], s2 = sinp[co + d + 64];

    size_t qo = ((size_t)bh * SEQ + s) * HD + d;
    float x1 = g_q[qo], x2 = g_q[qo + 64];
    float q1 = (x1 * c1 - x2 * s1) * qscale;
    float q2 = (x2 * c2 + x1 * s2) * qscale;
    bf16 h;
    h = __float2bfloat16(q1); g_qh[qo] = h;
    g_ql[qo] = __float2bfloat16(q1 - __bfloat162float(h));
    h = __float2bfloat16(q2); g_qh[qo + 64] = h;
    g_ql[qo + 64] = __float2bfloat16(q2 - __bfloat162float(h));

    x1 = g_k[qo]; x2 = g_k[qo + 64];
    float k1 = x1 * c1 - x2 * s1;
    float k2 = x2 * c2 + x1 * s2;
    h = __float2bfloat16(k1); g_kh[qo] = h;
    g_kl[qo] = __float2bfloat16(k1 - __bfloat162float(h));
    h = __float2bfloat16(k2); g_kh[qo + 64] = h;
    g_kl[qo + 64] = __float2bfloat16(k2 - __bfloat162float(h));
}

// ---------------------------------------------------------------------------
// Tensor-core causal flash attention (3-term bf16), 96KB smem (proven r6).
// ---------------------------------------------------------------------------
__global__ __launch_bounds__(256)
void attn_kernel()
{
    extern __shared__ char smem[];
    const uint32_t sa = smem_u32(smem);
    const int tid = threadIdx.x, lane = tid & 31, wid = tid >> 5;
    const int qt = blockIdx.x, bh = blockIdx.y;
    const int qbase = qt * 128;
    const int nk = 4 * (qt + 1);
    const int wm = wid * 16;

    {
        const int u = tid >> 7;
        const int row = tid & 127;
        const bf16* src = (u ? g_ql : g_qh) + ((size_t)bh * SEQ + qbase + row) * HD;
        const uint32_t dst = sa + u * 32768 + row * 256;
        const uint32_t swr = (uint32_t)((row & 7) << 4);
#pragma unroll
        for (int c = 0; c < 16; c++)
            CP_ASYNC16(dst + ((c * 16) ^ swr), src + c * 8);
        CP_COMMIT();
    }
    asm volatile("cp.async.wait_group 0;" ::: "memory");
    __syncthreads();

    uint32_t qh[8][4], ql[8][4];
    {
        const int arow = wm + (lane & 7) + ((lane >> 3) & 1) * 8;
        const uint32_t swr = (uint32_t)((arow & 7) << 4);
#pragma unroll
        for (int kt = 0; kt < 8; kt++) {
            const uint32_t c = (uint32_t)(kt * 2 + (lane >> 4));
            const uint32_t off = arow * 256 + ((c * 16) ^ swr);
            ldm_x4(qh[kt][0], qh[kt][1], qh[kt][2], qh[kt][3], sa + off);
            ldm_x4(ql[kt][0], ql[kt][1], ql[kt][2], ql[kt][3], sa + 32768 + off);
        }
    }
    __syncthreads();

    const int u4    = tid >> 6;
    const int krow  = (tid & 63) >> 1;
    const int halfc = tid & 1;
    const bf16* kvsrc =
        (u4 == 0 ? g_kh : u4 == 1 ? g_kl : u4 == 2 ? g_vh : g_vl) +
        (size_t)bh * SEQ * HD;
    const uint32_t kswr = (uint32_t)((krow & 7) << 4);

    auto issueKV = [&](int kt, int st) {
        const bf16* s = kvsrc + (size_t)(kt * 32 + krow) * HD + halfc * 64;
        const uint32_t dst = sa + st * 32768 + u4 * 8192 + krow * 256;
        const uint32_t cb = (uint32_t)(halfc * 128);
#pragma unroll
        for (int c = 0; c < 8; c++)
            CP_ASYNC16(dst + ((cb + c * 16) ^ kswr), s + c * 8);
    };

    issueKV(0, 0); CP_COMMIT();
    issueKV(1, 1); CP_COMMIT();

    float o[16][4];
#pragma unroll
    for (int nd = 0; nd < 16; nd++)
#pragma unroll
        for (int e = 0; e < 4; e++) o[nd][e] = 0.f;
    float m1 = -1e30f, m2 = -1e30f, l1 = 0.f, l2 = 0.f;

    const int brl  = ((lane >> 4) & 1) * 8 + (lane & 7);
    const int kobc = (lane >> 3) & 1;

#pragma unroll 1
    for (int kt = 0; kt < nk; kt++) {
        if (kt < nk - 1) asm volatile("cp.async.wait_group 1;" ::: "memory");
        else            asm volatile("cp.async.wait_group 0;" ::: "memory");
        __syncthreads();
        if (kt + 2 < nk) issueKV(kt + 2, (kt + 2) % 3);
        CP_COMMIT();

        const int rel = kt * 32 - qbase;
        if (rel > wm + 15) continue;

        const uint32_t kb = sa + (kt % 3) * 32768;

        float sacc[4][4];
#pragma unroll
        for (int nt = 0; nt < 4; nt++)
#pragma unroll
            for (int e = 0; e < 4; e++) sacc[nt][e] = 0.f;

#pragma unroll
        for (int kt16 = 0; kt16 < 8; kt16++) {
#pragma unroll
            for (int np = 0; np < 2; np++) {
                const int row = np * 16 + brl;
                const uint32_t sw = (uint32_t)((row & 7) << 4);
                const uint32_t off =
                    row * 256 + (((uint32_t)(kt16 * 2 + kobc) * 16) ^ sw);
                uint32_t h0, h1, h2, h3, e0, e1, e2, e3;
                ldm_x4(h0, h1, h2, h3, kb + off);
                ldm_x4(e0, e1, e2, e3, kb + 8192 + off);
                float* s0 = sacc[2 * np];
                float* s1 = sacc[2 * np + 1];
                mma_bf16(s0, qh[kt16][0], qh[kt16][1], qh[kt16][2], qh[kt16][3], h0, h1);
                mma_bf16(s0, qh[kt16][0], qh[kt16][1], qh[kt16][2], qh[kt16][3], e0, e1);
                mma_bf16(s0, ql[kt16][0], ql[kt16][1], ql[kt16][2], ql[kt16][3], h0, h1);
                mma_bf16(s1, qh[kt16][0], qh[kt16][1], qh[kt16][2], qh[kt16][3], h2, h3);
                mma_bf16(s1, qh[kt16][0], qh[kt16][1], qh[kt16][2], qh[kt16][3], e2, e3);
                mma_bf16(s1, ql[kt16][0], ql[kt16][1], ql[kt16][2], ql[kt16][3], h2, h3);
            }
        }

        if (rel + 31 > wm) {
            const int r1 = wm + (lane >> 2), r2 = r1 + 8;
#pragma unroll
            for (int nt = 0; nt < 4; nt++) {
                const int c0 = rel + nt * 8 + (lane & 3) * 2;
                if (c0     > r1) sacc[nt][0] = -1e30f;
                if (c0 + 1 > r1) sacc[nt][1] = -1e30f;
                if (c0     > r2) sacc[nt][2] = -1e30f;
                if (c0 + 1 > r2) sacc[nt][3] = -1e30f;
            }
        }

        float rmx1 = -1e30f, rmx2 = -1e30f;
#pragma unroll
        for (int nt = 0; nt < 4; nt++) {
            rmx1 = fmaxf(rmx1, fmaxf(sacc[nt][0], sacc[nt][1]));
            rmx2 = fmaxf(rmx2, fmaxf(sacc[nt][2], sacc[nt][3]));
        }
        rmx1 = fmaxf(rmx1, __shfl_xor_sync(0xffffffffu, rmx1, 1));
        rmx1 = fmaxf(rmx1, __shfl_xor_sync(0xffffffffu, rmx1, 2));
        rmx2 = fmaxf(rmx2, __shfl_xor_sync(0xffffffffu, rmx2, 1));
        rmx2 = fmaxf(rmx2, __shfl_xor_sync(0xffffffffu, rmx2, 2));

        const float nm1 = fmaxf(m1, rmx1), nm2 = fmaxf(m2, rmx2);
        const float corr1 = __expf(m1 - nm1), corr2 = __expf(m2 - nm2);
        m1 = nm1; m2 = nm2;

        float ps1 = 0.f, ps2 = 0.f;
#pragma unroll
        for (int nt = 0; nt < 4; nt++) {
            sacc[nt][0] = __expf(sacc[nt][0] - m1);
            sacc[nt][1] = __expf(sacc[nt][1] - m1);
            sacc[nt][2] = __expf(sacc[nt][2] - m2);
            sacc[nt][3] = __expf(sacc[nt][3] - m2);
            ps1 += sacc[nt][0] + sacc[nt][1];
            ps2 += sacc[nt][2] + sacc[nt][3];
        }
        ps1 += __shfl_xor_sync(0xffffffffu, ps1, 1);
        ps1 += __shfl_xor_sync(0xffffffffu, ps1, 2);
        ps2 += __shfl_xor_sync(0xffffffffu, ps2, 1);
        ps2 += __shfl_xor_sync(0xffffffffu, ps2, 2);
        l1 = l1 * corr1 + ps1;
        l2 = l2 * corr2 + ps2;

#pragma unroll
        for (int nd = 0; nd < 16; nd++) {
            o[nd][0] *= corr1; o[nd][1] *= corr1;
            o[nd][2] *= corr2; o[nd][3] *= corr2;
        }

        uint32_t pa[2][4], pl[2][4];
#pragma unroll
        for (int t = 0; t < 2; t++) {
            pa[t][0] = packsplit(sacc[2 * t][0],     sacc[2 * t][1],     pl[t][0]);
            pa[t][1] = packsplit(sacc[2 * t][2],     sacc[2 * t][3],     pl[t][1]);
            pa[t][2] = packsplit(sacc[2 * t + 1][0], sacc[2 * t + 1][1], pl[t][2]);
            pa[t][3] = packsplit(sacc[2 * t + 1][2], sacc[2 * t + 1][3], pl[t][3]);
        }

        const int kk15 = lane & 15;
        const int nhi  = (lane >> 4) * 8;
#pragma unroll
        for (int nd2 = 0; nd2 < 8; nd2++) {
#pragma unroll
            for (int t = 0; t < 2; t++) {
                const int kk = t * 16 + kk15;
                const int nn = nd2 * 16 + nhi;
                const uint32_t off =
                    kk * 256 + ((((uint32_t)(nn >> 3)) * 16) ^ ((uint32_t)((kk & 7) << 4)));
                uint32_t vh0, vh1, vh2, vh3, vl0, vl1, vl2, vl3;
                ldm_x4t(vh0, vh1, vh2, vh3, kb + 16384 + off);
                ldm_x4t(vl0, vl1, vl2, vl3, kb + 24576 + off);
                float* o0 = o[2 * nd2];
                float* o1 = o[2 * nd2 + 1];
                mma_bf16(o0, pa[t][0], pa[t][1], pa[t][2], pa[t][3], vh0, vh1);
                mma_bf16(o0, pa[t][0], pa[t][1], pa[t][2], pa[t][3], vl0, vl1);
                mma_bf16(o0, pl[t][0], pl[t][1], pl[t][2], pl[t][3], vh0, vh1);
                mma_bf16(o1, pa[t][0], pa[t][1], pa[t][2], pa[t][3], vh2, vh3);
                mma_bf16(o1, pa[t][0], pa[t][1], pa[t][2], pa[t][3], vl2, vl3);
                mma_bf16(o1, pl[t][0], pl[t][1], pl[t][2], pl[t][3], vh2, vh3);
            }
        }
    }

    const float inv1 = 1.f / l1, inv2 = 1.f / l2;
    const int b = bh >> 4, h = bh & 15;
    const int srow1 = qbase + wm + (lane >> 2);
    const size_t base1 = (size_t)(b * SEQ + srow1) * EMB + h * HD;
    const size_t base2 = base1 + (size_t)8 * EMB;
#pragma unroll
    for (int nd = 0; nd < 16; nd++) {
        const int d = nd * 8 + (lane & 3) * 2;
        uint32_t lo;
        uint32_t hi = packsplit(o[nd][0] * inv1, o[nd][1] * inv1, lo);
        *(uint32_t*)(g_ath + base1 + d) = hi;
        *(uint32_t*)(g_atl + base1 + d) = lo;
        hi = packsplit(o[nd][2] * inv2, o[nd][3] * inv2, lo);
        *(uint32_t*)(g_ath + base2 + d) = hi;
        *(uint32_t*)(g_atl + base2 + d) = lo;
    }
}

// ---------------------------------------------------------------------------
// Launcher
// ---------------------------------------------------------------------------
extern "C" void kernel_launch(void* const* d_in, const int* in_sizes, int n_in,
                              void* d_out, int out_size)
{
    (void)in_sizes; (void)n_in; (void)out_size;
    const float* X    = (const float*)d_in[0];
    const float* cosp = (const float*)d_in[1];
    const float* sinp = (const float*)d_in[2];
    const float* Wq   = (const float*)d_in[3];
    const float* Wk   = (const float*)d_in[4];
    const float* Wv   = (const float*)d_in[5];
    const float* Wo   = (const float*)d_in[6];
    float* out = (float*)d_out;

    float *q, *k;
    bf16 *xh, *xl, *ath, *atl, *wh, *wl, *vh;
    cudaGetSymbolAddress((void**)&q,   g_q);
    cudaGetSymbolAddress((void**)&k,   g_k);
    cudaGetSymbolAddress((void**)&xh,  g_xh);
    cudaGetSymbolAddress((void**)&xl,  g_xl);
    cudaGetSymbolAddress((void**)&ath, g_ath);
    cudaGetSymbolAddress((void**)&atl, g_atl);
    cudaGetSymbolAddress((void**)&wh,  g_wh);
    cudaGetSymbolAddress((void**)&wl,  g_wl);
    cudaGetSymbolAddress((void**)&vh,  g_vh);

    const int GEMM_SMEM = 2 * 32768;   // 65536 (2-stage, 2 CTAs/SM)
    const int ATT_SMEM  = 3 * 32768;   // 98304 (proven)
    cudaFuncSetAttribute(gemm_bf16<0>,
                         cudaFuncAttributeMaxDynamicSharedMemorySize, GEMM_SMEM);
    cudaFuncSetAttribute(gemm_bf16<1>,
                         cudaFuncAttributeMaxDynamicSharedMemorySize, GEMM_SMEM);
    cudaFuncSetAttribute(attn_kernel,
                         cudaFuncAttributeMaxDynamicSharedMemorySize, ATT_SMEM);

    // 1) split X; transpose+split weights
    split_kernel<<<(MTOT * EMB / 4) / 256, 256>>>(X, xh, xl);
    wsplit_kernel<<<dim3(EMB / 32, EMB / 32, 4), dim3(32, 8)>>>(Wq, Wk, Wv, Wo);

    // 2) QKV projections, one merged launch (z: 0->q fp32, 1->k fp32, 2->v bf16)
    gemm_bf16<1><<<dim3(EMB / 128, MTOT / 128, 3), 256, GEMM_SMEM>>>(
        xh, xl, wh, wl, q, vh, (bf16*)k);

    // 3) RoPE + split to bf16 hi/lo
    rope_split_kernel<<<(BATCHN * NH * SEQ * 64) / 256, 256>>>(cosp, sinp);

    // 4) tensor-core causal attention -> g_ath/g_atl
    attn_kernel<<<dim3(16, 32), 256, ATT_SMEM>>>();

    // 5) O projection
    gemm_bf16<0><<<dim3(EMB / 128, MTOT / 128), 256, GEMM_SMEM>>>(
        ath, atl, wh + 3 * (size_t)EMB * EMB, wl + 3 * (size_t)EMB * EMB,
        out, nullptr, nullptr);
}

// round 11
// speedup vs baseline: 7.3958x; 2.9660x over previous
#include <cuda_runtime.h>
#include <cuda_fp16.h>
#include <math.h>
#include <cstdint>

// Problem constants
#define BATCHN 2
#define SEQ    2048
#define EMB    2048
#define NH     16
#define HD     128
#define MTOT   (BATCHN * SEQ)   // 4096
#define BK     64
#define KITERS (EMB / BK)       // 32

typedef __half fp16;

// ---------------------------------------------------------------------------
// Scratch (static device globals: allocation-free)
// ---------------------------------------------------------------------------
__device__ float g_q[BATCHN * NH * SEQ * HD];    // fp32 q pre-rope [B,H,S,D]
__device__ float g_k[BATCHN * NH * SEQ * HD];    // fp32 k pre-rope
__device__ fp16 g_x16[MTOT * EMB];               // X in fp16
__device__ fp16 g_q16[BATCHN * NH * SEQ * HD];   // roped+scaled q fp16
__device__ fp16 g_k16[BATCHN * NH * SEQ * HD];   // roped k fp16
__device__ fp16 g_v16[BATCHN * NH * SEQ * HD];   // v fp16 (gemm direct)
__device__ fp16 g_att16[MTOT * EMB];             // attention out fp16 [B,S,H*D]
__device__ fp16 g_w16[4 * EMB * EMB];            // W^T fp16, [n][k]

// ---------------------------------------------------------------------------
// Helpers
// ---------------------------------------------------------------------------
__device__ __forceinline__ uint32_t smem_u32(const void* p) {
    uint32_t a;
    asm("{ .reg .u64 t; cvta.to.shared.u64 t, %1; cvt.u32.u64 %0, t; }"
        : "=r"(a) : "l"(p));
    return a;
}

__device__ __forceinline__ void ldm_x4(uint32_t& r0, uint32_t& r1,
                                       uint32_t& r2, uint32_t& r3, uint32_t a) {
    asm volatile("ldmatrix.sync.aligned.m8n8.x4.shared.b16 {%0,%1,%2,%3}, [%4];"
                 : "=r"(r0), "=r"(r1), "=r"(r2), "=r"(r3) : "r"(a));
}

__device__ __forceinline__ void ldm_x4t(uint32_t& r0, uint32_t& r1,
                                        uint32_t& r2, uint32_t& r3, uint32_t a) {
    asm volatile("ldmatrix.sync.aligned.m8n8.x4.trans.shared.b16 {%0,%1,%2,%3}, [%4];"
                 : "=r"(r0), "=r"(r1), "=r"(r2), "=r"(r3) : "r"(a));
}

__device__ __forceinline__ void mma_f16(float* c, uint32_t a0, uint32_t a1,
                                        uint32_t a2, uint32_t a3,
                                        uint32_t b0, uint32_t b1) {
    asm volatile("mma.sync.aligned.m16n8k16.row.col.f32.f16.f16.f32 "
                 "{%0,%1,%2,%3}, {%4,%5,%6,%7}, {%8,%9}, {%0,%1,%2,%3};"
                 : "+f"(c[0]), "+f"(c[1]), "+f"(c[2]), "+f"(c[3])
                 : "r"(a0), "r"(a1), "r"(a2), "r"(a3), "r"(b0), "r"(b1));
}

#define CP_ASYNC16(dst, src) \
    asm volatile("cp.async.cg.shared.global [%0], [%1], 16;" \
                 :: "r"(dst), "l"(src) : "memory")
#define CP_COMMIT() asm volatile("cp.async.commit_group;" ::: "memory")

__device__ __forceinline__ uint32_t packh2(float x, float y) {
    __half2 h = __floats2half2_rn(x, y);
    uint32_t u;
    memcpy(&u, &h, 4);
    return u;
}

// ---------------------------------------------------------------------------
// Convert fp32 -> fp16 (elementwise, 4 per thread)
// ---------------------------------------------------------------------------
__global__ void cvt_kernel(const float* __restrict__ src, fp16* __restrict__ dst)
{
    int i = blockIdx.x * blockDim.x + threadIdx.x;
    float4 v = ((const float4*)src)[i];
    ((uint32_t*)dst)[2 * i]     = packh2(v.x, v.y);
    ((uint32_t*)dst)[2 * i + 1] = packh2(v.z, v.w);
}

// ---------------------------------------------------------------------------
// Transpose + convert weights: g_w16[z][n*EMB + k] = fp16(W_z[k*EMB + n])
// ---------------------------------------------------------------------------
__global__ void wcvt_kernel(const float* __restrict__ Wq,
                            const float* __restrict__ Wk,
                            const float* __restrict__ Wv,
                            const float* __restrict__ Wo)
{
    __shared__ float t[32][33];
    const int z = blockIdx.z;
    const float* W = (z == 0) ? Wq : (z == 1) ? Wk : (z == 2) ? Wv : Wo;
    fp16* O = g_w16 + (size_t)z * EMB * EMB;

    int x  = blockIdx.x * 32 + threadIdx.x;
    int y0 = blockIdx.y * 32;
#pragma unroll
    for (int j = 0; j < 32; j += 8)
        t[threadIdx.y + j][threadIdx.x] = W[(size_t)(y0 + threadIdx.y + j) * EMB + x];
    __syncthreads();
    int ox = y0 + threadIdx.x;
#pragma unroll
    for (int j = 0; j < 32; j += 8) {
        int oy = blockIdx.x * 32 + threadIdx.y + j;
        O[(size_t)oy * EMB + ox] = __float2half(t[threadIdx.x][threadIdx.y + j]);
    }
}

// ---------------------------------------------------------------------------
// fp16 GEMM via mma.sync: C[4096,2048] = A @ Bt^T.
// 128x128 tile, BK=64 (128B rows = swizzle atom), 2-stage cp.async (64KB),
// __launch_bounds__(256,2) -> 2 CTAs/SM.
// QKV=1: grid.z selects weight z and destination:
//        z=0 -> fp32 g_q [B,H,S,D] (via C); z=1 -> fp32 g_k (via Ck);
//        z=2 -> fp16 g_v16 (via Ch).
// QKV=0: fp32 row-major C.
// smem stage (32KB): A 128 rows x 128B | B 128 rows x 128B.
// ---------------------------------------------------------------------------
template <int QKV>
__global__ __launch_bounds__(256, 2)
void gemm_fp16(const fp16* __restrict__ A, const fp16* __restrict__ B0,
               float* __restrict__ C, fp16* __restrict__ Ch,
               float* __restrict__ Ck)
{
    extern __shared__ char smem[];
    const uint32_t sa = smem_u32(smem);
    const int tid  = threadIdx.x;
    const int lane = tid & 31;
    const int wid  = tid >> 5;
    const int m0 = blockIdx.y * 128;
    const int n0 = blockIdx.x * 128;
    const int z  = QKV ? blockIdx.z : 0;

    const fp16* B = B0 + (size_t)z * EMB * EMB;

    // loader: thread -> (row r, 4x16B chunk set)
    const int r    = tid >> 1;
    const int cset = (tid & 1) * 4;
    const fp16* agm = A + (size_t)(m0 + r) * EMB;
    const fp16* bgm = B + (size_t)(n0 + r) * EMB;
    const uint32_t swr = (uint32_t)((r & 7) << 4);

    auto issue = [&](int it, int stage) {
        const int k0 = it * BK;
        const uint32_t abase = sa + stage * 32768 + r * 128;
        const uint32_t bbase = abase + 16384;
#pragma unroll
        for (int c = 0; c < 4; c++) {
            const int ch = cset + c;
            const uint32_t sw = ((uint32_t)(ch * 16)) ^ swr;
            CP_ASYNC16(abase + sw, agm + k0 + ch * 8);
            CP_ASYNC16(bbase + sw, bgm + k0 + ch * 8);
        }
    };

    const int wm = (wid & 1) * 64;
    const int wn = (wid >> 1) * 32;
    const int arl = (lane & 7) + ((lane >> 3) & 1) * 8;
    const int koa = (lane >> 4) * 16;
    const int brl = ((lane >> 4) & 1) * 8 + (lane & 7);
    const int kob = ((lane >> 3) & 1) * 16;

    float acc[4][4][4];
#pragma unroll
    for (int mt = 0; mt < 4; mt++)
#pragma unroll
        for (int nt = 0; nt < 4; nt++)
#pragma unroll
            for (int e = 0; e < 4; e++) acc[mt][nt][e] = 0.f;

    issue(0, 0); CP_COMMIT();
    issue(1, 1); CP_COMMIT();

#pragma unroll 1
    for (int it = 0; it < KITERS; it++) {
        asm volatile("cp.async.wait_group 1;" ::: "memory");
        __syncthreads();

        const uint32_t ab = sa + (it & 1) * 32768;
        const uint32_t bb = ab + 16384;
#pragma unroll
        for (int s16 = 0; s16 < 4; s16++) {
            uint32_t ah[4][4];
#pragma unroll
            for (int mt = 0; mt < 4; mt++) {
                const int row = wm + mt * 16 + arl;
                const uint32_t ih = (uint32_t)(s16 * 32 + koa);
                ldm_x4(ah[mt][0], ah[mt][1], ah[mt][2], ah[mt][3],
                       ab + row * 128 + (ih ^ ((uint32_t)((row & 7) << 4))));
            }
#pragma unroll
            for (int np = 0; np < 2; np++) {
                const int row = wn + np * 16 + brl;
                const uint32_t ih = (uint32_t)(s16 * 32 + kob);
                uint32_t b0, b1, b2, b3;
                ldm_x4(b0, b1, b2, b3,
                       bb + row * 128 + (ih ^ ((uint32_t)((row & 7) << 4))));
#pragma unroll
                for (int mt = 0; mt < 4; mt++) {
                    mma_f16(acc[mt][2 * np],
                            ah[mt][0], ah[mt][1], ah[mt][2], ah[mt][3], b0, b1);
                    mma_f16(acc[mt][2 * np + 1],
                            ah[mt][0], ah[mt][1], ah[mt][2], ah[mt][3], b2, b3);
                }
            }
        }
        __syncthreads();
        if (it + 2 < KITERS) { issue(it + 2, it & 1); }
        CP_COMMIT();
    }

    // Epilogue
    const int g = lane >> 2, tig = lane & 3;
#pragma unroll
    for (int mt = 0; mt < 4; mt++) {
        const int m = m0 + wm + mt * 16 + g;
#pragma unroll
        for (int nt = 0; nt < 4; nt++) {
            const int col = wn + nt * 8 + 2 * tig;
            float2 v0 = make_float2(acc[mt][nt][0], acc[mt][nt][1]);
            float2 v1 = make_float2(acc[mt][nt][2], acc[mt][nt][3]);
            if (!QKV) {
                float* p = C + (size_t)m * EMB + n0 + col;
                *(float2*)p = v0;
                *(float2*)(p + (size_t)8 * EMB) = v1;
            } else {
                const int b = m >> 11, si = m & 2047, h = n0 >> 7;
                const size_t base = ((size_t)(b * NH + h) * SEQ + si) * HD + col;
                if (z < 2) {
                    float* dst = (z == 0 ? C : Ck);
                    *(float2*)(dst + base) = v0;
                    *(float2*)(dst + base + 8 * HD) = v1;
                } else {
                    *(uint32_t*)(Ch + base)          = packh2(v0.x, v0.y);
                    *(uint32_t*)(Ch + base + 8 * HD) = packh2(v1.x, v1.y);
                }
            }
        }
    }
}

// ---------------------------------------------------------------------------
// RoPE + convert: read fp32 g_q/g_k, write fp16 (q scaled by 1/sqrt(HD)).
// ---------------------------------------------------------------------------
__global__ void rope_cvt_kernel(const float* __restrict__ cosp,
                                const float* __restrict__ sinp)
{
    int gid = blockIdx.x * blockDim.x + threadIdx.x;
    int d  = gid & 63;
    int s  = (gid >> 6) & (SEQ - 1);
    int bh = gid >> 17;
    int b  = bh >> 4;
    const float qscale = 0.08838834764831845f;

    int co = (b * SEQ + s) * HD;
    float c1 = cosp[co + d],      s1 = sinp[co + d];
    float c2 = cosp[co + d + 64], s2 = sinp[co + d + 64];

    size_t qo = ((size_t)bh * SEQ + s) * HD + d;
    float x1 = g_q[qo], x2 = g_q[qo + 64];
    g_q16[qo]      = __float2half((x1 * c1 - x2 * s1) * qscale);
    g_q16[qo + 64] = __float2half((x2 * c2 + x1 * s2) * qscale);

    x1 = g_k[qo]; x2 = g_k[qo + 64];
    g_k16[qo]      = __float2half(x1 * c1 - x2 * s1);
    g_k16[qo + 64] = __float2half(x2 * c2 + x1 * s2);
}

// ---------------------------------------------------------------------------
// fp16 tensor-core causal flash attention (r9 structure, single-term).
// BM=128 (8 warps x m16), BN=32, D=128.  smem: 3 stages x 16KB
// (stage = K 32x256B | V 32x256B); Q staged through stages 0-1 (32KB),
// then held as register fragments.  Output fp16 -> g_att16 [B,S,H*D].
// ---------------------------------------------------------------------------
__global__ __launch_bounds__(256)
void attn_kernel()
{
    extern __shared__ char smem[];
    const uint32_t sa = smem_u32(smem);
    const int tid = threadIdx.x, lane = tid & 31, wid = tid >> 5;
    const int qt = blockIdx.x, bh = blockIdx.y;
    const int qbase = qt * 128;
    const int nk = 4 * (qt + 1);
    const int wm = wid * 16;

    // ---- Load Q into stages 0-1 (128 rows x 256B, swizzled)
    {
        const int row   = tid >> 1;
        const int halfc = tid & 1;
        const fp16* src = g_q16 + ((size_t)bh * SEQ + qbase + row) * HD + halfc * 64;
        const uint32_t dst = sa + row * 256;
        const uint32_t cb  = (uint32_t)(halfc * 128);
        const uint32_t swr = (uint32_t)((row & 7) << 4);
#pragma unroll
        for (int c = 0; c < 8; c++)
            CP_ASYNC16(dst + ((cb + c * 16) ^ swr), src + c * 8);
        CP_COMMIT();
    }
    asm volatile("cp.async.wait_group 0;" ::: "memory");
    __syncthreads();

    // ---- Extract Q fragments (m16k16 x 8)
    uint32_t qf[8][4];
    {
        const int arow = wm + (lane & 7) + ((lane >> 3) & 1) * 8;
        const uint32_t swr = (uint32_t)((arow & 7) << 4);
#pragma unroll
        for (int kt = 0; kt < 8; kt++) {
            const uint32_t c = (uint32_t)(kt * 2 + (lane >> 4));
            ldm_x4(qf[kt][0], qf[kt][1], qf[kt][2], qf[kt][3],
                   sa + arow * 256 + ((c * 16) ^ swr));
        }
    }
    __syncthreads();   // stages 0-1 free for KV reuse

    // ---- KV loader: u2 = K/V (8KB each: 32 rows x 256B)
    const int u2   = tid >> 7;
    const int krow = (tid & 127) >> 2;
    const int cset = (tid & 3) * 4;
    const fp16* kvsrc = (u2 ? g_v16 : g_k16) + (size_t)bh * SEQ * HD;
    const uint32_t kswr = (uint32_t)((krow & 7) << 4);

    auto issueKV = [&](int kt, int st) {
        const fp16* s = kvsrc + (size_t)(kt * 32 + krow) * HD;
        const uint32_t dst = sa + st * 16384 + u2 * 8192 + krow * 256;
#pragma unroll
        for (int c = 0; c < 4; c++) {
            const int ch = cset + c;
            CP_ASYNC16(dst + (((uint32_t)(ch * 16)) ^ kswr), s + ch * 8);
        }
    };

    issueKV(0, 0); CP_COMMIT();
    issueKV(1, 1); CP_COMMIT();

    float o[16][4];
#pragma unroll
    for (int nd = 0; nd < 16; nd++)
#pragma unroll
        for (int e = 0; e < 4; e++) o[nd][e] = 0.f;
    float m1 = -1e30f, m2 = -1e30f, l1 = 0.f, l2 = 0.f;

    const int brl  = ((lane >> 4) & 1) * 8 + (lane & 7);
    const int kobc = (lane >> 3) & 1;

#pragma unroll 1
    for (int kt = 0; kt < nk; kt++) {
        if (kt < nk - 1) asm volatile("cp.async.wait_group 1;" ::: "memory");
        else            asm volatile("cp.async.wait_group 0;" ::: "memory");
        __syncthreads();
        if (kt + 2 < nk) issueKV(kt + 2, (kt + 2) % 3);
        CP_COMMIT();

        const int rel = kt * 32 - qbase;
        if (rel > wm + 15) continue;

        const uint32_t kb = sa + (kt % 3) * 16384;

        // ---- S = Q . K^T
        float sacc[4][4];
#pragma unroll
        for (int nt = 0; nt < 4; nt++)
#pragma unroll
            for (int e = 0; e < 4; e++) sacc[nt][e] = 0.f;

#pragma unroll
        for (int kt16 = 0; kt16 < 8; kt16++) {
#pragma unroll
            for (int np = 0; np < 2; np++) {
                const int row = np * 16 + brl;
                const uint32_t off = row * 256 +
                    (((uint32_t)((kt16 * 2 + kobc) * 16)) ^ ((uint32_t)((row & 7) << 4)));
                uint32_t b0, b1, b2, b3;
                ldm_x4(b0, b1, b2, b3, kb + off);
                mma_f16(sacc[2 * np],
                        qf[kt16][0], qf[kt16][1], qf[kt16][2], qf[kt16][3], b0, b1);
                mma_f16(sacc[2 * np + 1],
                        qf[kt16][0], qf[kt16][1], qf[kt16][2], qf[kt16][3], b2, b3);
            }
        }

        // ---- causal mask
        if (rel + 31 > wm) {
            const int r1 = wm + (lane >> 2), r2 = r1 + 8;
#pragma unroll
            for (int nt = 0; nt < 4; nt++) {
                const int c0 = rel + nt * 8 + (lane & 3) * 2;
                if (c0     > r1) sacc[nt][0] = -1e30f;
                if (c0 + 1 > r1) sacc[nt][1] = -1e30f;
                if (c0     > r2) sacc[nt][2] = -1e30f;
                if (c0 + 1 > r2) sacc[nt][3] = -1e30f;
            }
        }

        // ---- online softmax
        float rmx1 = -1e30f, rmx2 = -1e30f;
#pragma unroll
        for (int nt = 0; nt < 4; nt++) {
            rmx1 = fmaxf(rmx1, fmaxf(sacc[nt][0], sacc[nt][1]));
            rmx2 = fmaxf(rmx2, fmaxf(sacc[nt][2], sacc[nt][3]));
        }
        rmx1 = fmaxf(rmx1, __shfl_xor_sync(0xffffffffu, rmx1, 1));
        rmx1 = fmaxf(rmx1, __shfl_xor_sync(0xffffffffu, rmx1, 2));
        rmx2 = fmaxf(rmx2, __shfl_xor_sync(0xffffffffu, rmx2, 1));
        rmx2 = fmaxf(rmx2, __shfl_xor_sync(0xffffffffu, rmx2, 2));

        const float nm1 = fmaxf(m1, rmx1), nm2 = fmaxf(m2, rmx2);
        const float corr1 = __expf(m1 - nm1), corr2 = __expf(m2 - nm2);
        m1 = nm1; m2 = nm2;

        float ps1 = 0.f, ps2 = 0.f;
#pragma unroll
        for (int nt = 0; nt < 4; nt++) {
            sacc[nt][0] = __expf(sacc[nt][0] - m1);
            sacc[nt][1] = __expf(sacc[nt][1] - m1);
            sacc[nt][2] = __expf(sacc[nt][2] - m2);
            sacc[nt][3] = __expf(sacc[nt][3] - m2);
            ps1 += sacc[nt][0] + sacc[nt][1];
            ps2 += sacc[nt][2] + sacc[nt][3];
        }
        ps1 += __shfl_xor_sync(0xffffffffu, ps1, 1);
        ps1 += __shfl_xor_sync(0xffffffffu, ps1, 2);
        ps2 += __shfl_xor_sync(0xffffffffu, ps2, 1);
        ps2 += __shfl_xor_sync(0xffffffffu, ps2, 2);
        l1 = l1 * corr1 + ps1;
        l2 = l2 * corr2 + ps2;

#pragma unroll
        for (int nd = 0; nd < 16; nd++) {
            o[nd][0] *= corr1; o[nd][1] *= corr1;
            o[nd][2] *= corr2; o[nd][3] *= corr2;
        }

        // ---- P fragments (C-layout -> A-layout), fp16
        uint32_t pa[2][4];
#pragma unroll
        for (int t = 0; t < 2; t++) {
            pa[t][0] = packh2(sacc[2 * t][0],     sacc[2 * t][1]);
            pa[t][1] = packh2(sacc[2 * t][2],     sacc[2 * t][3]);
            pa[t][2] = packh2(sacc[2 * t + 1][0], sacc[2 * t + 1][1]);
            pa[t][3] = packh2(sacc[2 * t + 1][2], sacc[2 * t + 1][3]);
        }

        // ---- O += P . V
        const int kk15 = lane & 15;
        const int nhi  = (lane >> 4) * 8;
#pragma unroll
        for (int nd2 = 0; nd2 < 8; nd2++) {
#pragma unroll
            for (int t = 0; t < 2; t++) {
                const int kk = t * 16 + kk15;
                const int nn = nd2 * 16 + nhi;
                const uint32_t off = kk * 256 +
                    ((((uint32_t)(nn >> 3)) * 16) ^ ((uint32_t)((kk & 7) << 4)));
                uint32_t v0, v1, v2, v3;
                ldm_x4t(v0, v1, v2, v3, kb + 8192 + off);
                mma_f16(o[2 * nd2],     pa[t][0], pa[t][1], pa[t][2], pa[t][3], v0, v1);
                mma_f16(o[2 * nd2 + 1], pa[t][0], pa[t][1], pa[t][2], pa[t][3], v2, v3);
            }
        }
    }

    // ---- epilogue: normalize, store fp16 [B,S,H*D]
    const float inv1 = 1.f / l1, inv2 = 1.f / l2;
    const int b = bh >> 4, h = bh & 15;
    const int srow1 = qbase + wm + (lane >> 2);
    const size_t base1 = (size_t)(b * SEQ + srow1) * EMB + h * HD;
    const size_t base2 = base1 + (size_t)8 * EMB;
#pragma unroll
    for (int nd = 0; nd < 16; nd++) {
        const int d = nd * 8 + (lane & 3) * 2;
        *(uint32_t*)(g_att16 + base1 + d) = packh2(o[nd][0] * inv1, o[nd][1] * inv1);
        *(uint32_t*)(g_att16 + base2 + d) = packh2(o[nd][2] * inv2, o[nd][3] * inv2);
    }
}

// ---------------------------------------------------------------------------
// Launcher
// ---------------------------------------------------------------------------
extern "C" void kernel_launch(void* const* d_in, const int* in_sizes, int n_in,
                              void* d_out, int out_size)
{
    (void)in_sizes; (void)n_in; (void)out_size;
    const float* X    = (const float*)d_in[0];
    const float* cosp = (const float*)d_in[1];
    const float* sinp = (const float*)d_in[2];
    const float* Wq   = (const float*)d_in[3];
    const float* Wk   = (const float*)d_in[4];
    const float* Wv   = (const float*)d_in[5];
    const float* Wo   = (const float*)d_in[6];
    float* out = (float*)d_out;

    float *q, *k;
    fp16 *x16, *att16, *w16, *v16;
    cudaGetSymbolAddress((void**)&q,     g_q);
    cudaGetSymbolAddress((void**)&k,     g_k);
    cudaGetSymbolAddress((void**)&x16,   g_x16);
    cudaGetSymbolAddress((void**)&att16, g_att16);
    cudaGetSymbolAddress((void**)&w16,   g_w16);
    cudaGetSymbolAddress((void**)&v16,   g_v16);

    const int GEMM_SMEM = 2 * 32768;   // 65536 (2-stage, 2 CTAs/SM)
    const int ATT_SMEM  = 3 * 16384;   // 49152
    cudaFuncSetAttribute(gemm_fp16<0>,
                         cudaFuncAttributeMaxDynamicSharedMemorySize, GEMM_SMEM);
    cudaFuncSetAttribute(gemm_fp16<1>,
                         cudaFuncAttributeMaxDynamicSharedMemorySize, GEMM_SMEM);
    cudaFuncSetAttribute(attn_kernel,
                         cudaFuncAttributeMaxDynamicSharedMemorySize, ATT_SMEM);

    // 1) convert X; transpose+convert weights
    cvt_kernel<<<(MTOT * EMB / 4) / 256, 256>>>(X, x16);
    wcvt_kernel<<<dim3(EMB / 32, EMB / 32, 4), dim3(32, 8)>>>(Wq, Wk, Wv, Wo);

    // 2) QKV projections, one merged launch (z: 0->q fp32, 1->k fp32, 2->v fp16)
    gemm_fp16<1><<<dim3(EMB / 128, MTOT / 128, 3), 256, GEMM_SMEM>>>(
        x16, w16, q, v16, k);

    // 3) RoPE + convert to fp16
    rope_cvt_kernel<<<(BATCHN * NH * SEQ * 64) / 256, 256>>>(cosp, sinp);

    // 4) fp16 tensor-core causal attention -> g_att16
    attn_kernel<<<dim3(16, 32), 256, ATT_SMEM>>>();

    // 5) O projection
    gemm_fp16<0><<<dim3(EMB / 128, MTOT / 128), 256, GEMM_SMEM>>>(
        att16, w16 + 3 * (size_t)EMB * EMB, out, nullptr, nullptr);
}